// round 11
// baseline (speedup 1.0000x reference)
#include <cuda_runtime.h>
#include <cstdint>
#include <math.h>

// ---------------------------------------------------------------------------
// Problem constants
// ---------------------------------------------------------------------------
constexpr int Bc = 8;
constexpr int C  = 1024;
constexpr int Ci = 512;
constexpr int Nd = 48 * 48;          // 2304
constexpr int Na = 16 * 16;          // 256
constexpr int R  = 64;               // C / 16
constexpr float BN_INV = 0.9999950000374997f;  // 1/sqrt(1+1e-5)

// ---------------------------------------------------------------------------
// Device scratch (static)
// ---------------------------------------------------------------------------
__device__ float g_detT  [Bc * Nd * C];    // rounded tf32
__device__ float g_aimT  [Bc * Na * C];    // rounded tf32
__device__ float g_dx    [Bc * Ci * Nd];
__device__ float g_phx   [Bc * Nd * Ci];
__device__ float g_ax    [Bc * Ci * Na];
__device__ float g_thx   [Bc * Na * Ci];
__device__ float g_fm    [Bc * Na * Nd];
__device__ float g_fT    [Bc * Nd * Na];
__device__ float g_nap   [Bc * Na * Ci];
__device__ float g_ndp   [Bc * Nd * Ci];
__device__ float g_nonaim[Bc * C  * Na];
__device__ float g_pooled[Bc * 2  * C];
// rounded weight copies
__device__ float g_gwr [Ci * C];
__device__ float g_thwr[Ci * C];
__device__ float g_phwr[Ci * C];
__device__ float g_Wwr [C * Ci];
__device__ float g_Qwr [C * Ci];

// ---------------------------------------------------------------------------
// helpers
// ---------------------------------------------------------------------------
__device__ __forceinline__ uint32_t f2tf(float x) {
    uint32_t r;
    asm("cvt.rna.tf32.f32 %0, %1;" : "=r"(r) : "f"(x));
    return r;
}
__device__ __forceinline__ float rnd_tf(float x) {
    return __uint_as_float(f2tf(x));
}
__device__ __forceinline__ uint32_t smem_u32(const void* p) {
    uint32_t a;
    asm("{ .reg .u64 t; cvta.to.shared.u64 t, %1; cvt.u32.u64 %0, t; }" : "=r"(a) : "l"(p));
    return a;
}
__device__ __forceinline__ void mma8(float* d, const uint32_t* a, const uint32_t* b) {
    asm volatile(
        "mma.sync.aligned.m16n8k8.row.col.f32.tf32.tf32.f32 "
        "{%0,%1,%2,%3}, {%4,%5,%6,%7}, {%8,%9}, {%0,%1,%2,%3};"
        : "+f"(d[0]), "+f"(d[1]), "+f"(d[2]), "+f"(d[3])
        : "r"(a[0]), "r"(a[1]), "r"(a[2]), "r"(a[3]), "r"(b[0]), "r"(b[1]));
}
__device__ __forceinline__ void ldsm4(uint32_t* r, uint32_t a) {
    asm volatile("ldmatrix.sync.aligned.m8n8.x4.shared.b16 {%0,%1,%2,%3}, [%4];"
        : "=r"(r[0]), "=r"(r[1]), "=r"(r[2]), "=r"(r[3]) : "r"(a));
}
__device__ __forceinline__ void cpa16(uint32_t s, const void* g) {
    asm volatile("cp.async.cg.shared.global [%0], [%1], 16;" :: "r"(s), "l"(g));
}
#define CPA_COMMIT() asm volatile("cp.async.commit_group;" ::: "memory")
#define CPA_WAIT1()  asm volatile("cp.async.wait_group 1;" ::: "memory")

// ---------------------------------------------------------------------------
// tf32 mma.sync GEMM:  D[M,N] = alpha * A[M,K] * B[N,K]^T  (+ epilogue)
//   Block 128x128, 8 warps (4m x 2n), warp tile 32x64, BK=32, 3-stage
//   cp.async pipeline (halves per-K sync/wait events vs BK=16).
//   Fragment loads via ldmatrix.x4 (layout verified bit-exact in R10).
//   Inputs MUST be tf32-pre-rounded fp32 (cp.async truncation then exact).
//   Smem k-stride 36 words: ldmatrix phase banks = (4r + c) mod 32,
//   r=0..7 4-word runs -> all 32 banks exactly once, conflict-free.
//   Requires M%128==0, N%128==0, K%32==0, row strides == K.
//   EPI 0: alpha*acc (+ bM[m] if BMODE==1, + bN[n] if BMODE==2)
//          RND=1 -> output rounded to tf32 (GEMM-feeding intermediates)
//   EPI 1: bng[m]*BN_INV*(acc+bM[m]) + bnb[m] + resid[m*ldc+n]
//   EPI 2: EPI1 value v; additionally out2 = v * cw[bz*M + m]
// ---------------------------------------------------------------------------
constexpr int SA     = 36;                 // padded k-stride in words (32 + 4)
constexpr int AW     = 128 * SA;           // words of A per stage
constexpr int STAGEW = 256 * SA;           // words per stage (A then B)
constexpr int STAGEB = STAGEW * 4;         // 36864 bytes per stage
constexpr int NSTG   = 3;
constexpr int GSMEM  = NSTG * STAGEB;      // 110592 B (2 CTAs/SM: 221KB<228KB)

template<int EPI, int BMODE, int RND>
__global__ void __launch_bounds__(256, 2)
tgemm(const float* __restrict__ A, const float* __restrict__ B,
      float* __restrict__ Co,
      int K, int ldc, long strA, long strB, long strC, float alpha,
      const float* __restrict__ bM, const float* __restrict__ bN,
      const float* __restrict__ bng, const float* __restrict__ bnb,
      const float* __restrict__ resid, long sR,
      const float* __restrict__ cw, float* __restrict__ out2)
{
    extern __shared__ uint32_t sm[];
    const uint32_t smb = smem_u32(sm);

    const int tid = threadIdx.x, lane = tid & 31, wid = tid >> 5;
    const int wm = wid & 3, wn = wid >> 2;          // warp grid 4(m) x 2(n)
    const int bz = blockIdx.z;
    const int bm = blockIdx.y * 128, bn = blockIdx.x * 128;

    // loader: thread t<128 -> A row t; t>=128 -> B row t-128; 128 B each (BK=32)
    const int lrow = tid & 127;
    const bool isA = tid < 128;
    const float* gbase = isA
        ? A + (long)bz * strA + (long)(bm + lrow) * K
        : B + (long)bz * strB + (long)(bn + lrow) * K;
    const uint32_t sbase = smb + (uint32_t)(((isA ? 0 : AW) + lrow * SA) * 4);

    auto loadt = [&](int kt, int st) {
        const float* gp = gbase + kt * 32;
        const uint32_t sp = sbase + (uint32_t)(st * STAGEB);
        #pragma unroll
        for (int j = 0; j < 8; j++) cpa16(sp + j * 16, gp + j * 4);
    };

    // ldmatrix per-thread base addresses (stage 0, k8 = 0) — as validated R10:
    // A: row = wm*32 + (lane & 15), colw = 4*(lane >> 4)
    // B: row = wn*64 + (lane & 7) + 8*(lane >> 4), colw = 4*((lane >> 3) & 1)
    const uint32_t aAddr = smb +
        (uint32_t)(((wm * 32 + (lane & 15)) * SA + 4 * (lane >> 4)) * 4);
    const uint32_t bAddr = smb +
        (uint32_t)((AW + (wn * 64 + (lane & 7) + 8 * (lane >> 4)) * SA
                    + 4 * ((lane >> 3) & 1)) * 4);

    float acc[2][8][4];
    #pragma unroll
    for (int i = 0; i < 2; i++)
        #pragma unroll
        for (int j = 0; j < 8; j++)
            #pragma unroll
            for (int q = 0; q < 4; q++) acc[i][j][q] = 0.f;

    auto compute = [&](int st) {
        const uint32_t stoff = (uint32_t)(st * STAGEB);
        #pragma unroll
        for (int k8 = 0; k8 < 4; k8++) {                     // BK=32 -> 4 k8
            const uint32_t kboff = stoff + (uint32_t)(k8 * 32);   // 8 words
            uint32_t af[2][4];
            ldsm4(af[0], aAddr + kboff);
            ldsm4(af[1], aAddr + kboff + 16 * SA * 4);
            uint32_t bf[4][4];
            #pragma unroll
            for (int p = 0; p < 4; p++)
                ldsm4(bf[p], bAddr + kboff + (uint32_t)(p * 16 * SA * 4));
            #pragma unroll
            for (int ni = 0; ni < 8; ni++) {
                const uint32_t* bb = &bf[ni >> 1][(ni & 1) * 2];
                mma8(acc[0][ni], af[0], bb);
                mma8(acc[1][ni], af[1], bb);
            }
        }
    };

    const int nk = K / 32;          // >= 8 for all GEMMs here
    loadt(0, 0); CPA_COMMIT();
    loadt(1, 1); CPA_COMMIT();

    for (int kt = 0; kt < nk; kt++) {
        const int s = kt % 3;
        CPA_WAIT1();                 // group kt complete (one commit/iter)
        __syncthreads();             // writes visible; prev compute done
        if (kt + 2 < nk) loadt(kt + 2, (kt + 2) % 3);
        CPA_COMMIT();                // commit every iter (possibly empty)
        compute(s);
    }

    // ---- epilogue ----
    const int g = lane >> 2, t2 = (lane & 3) * 2;
    #pragma unroll
    for (int mi = 0; mi < 2; mi++) {
        #pragma unroll
        for (int half = 0; half < 2; half++) {
            const int m = bm + wm * 32 + mi * 16 + half * 8 + g;
            float addM = 0.f, sc = 1.f, be = 0.f, gwv = 0.f;
            if constexpr (EPI == 0) {
                if constexpr (BMODE == 1) addM = bM[m];
            } else {
                addM = bM[m]; sc = bng[m] * BN_INV; be = bnb[m];
            }
            float* crow = Co + (long)bz * strC + (long)m * ldc;
            const float* rrow = nullptr;
            float* o2row = nullptr;
            if constexpr (EPI >= 1) rrow = resid + (long)bz * sR + (long)m * ldc;
            if constexpr (EPI == 2) {
                o2row = out2 + (long)bz * strC + (long)m * ldc;
                gwv = cw[(long)bz * (gridDim.y * 128) + m];
            }
            #pragma unroll
            for (int ni = 0; ni < 8; ni++) {
                const int n = bn + wn * 64 + ni * 8 + t2;
                const float c0 = acc[mi][ni][half * 2 + 0];
                const float c1 = acc[mi][ni][half * 2 + 1];
                float2 o;
                if constexpr (EPI == 0) {
                    o.x = alpha * c0 + addM;
                    o.y = alpha * c1 + addM;
                    if constexpr (BMODE == 2) { o.x += bN[n]; o.y += bN[n + 1]; }
                    if constexpr (RND == 1) { o.x = rnd_tf(o.x); o.y = rnd_tf(o.y); }
                } else {
                    float2 rv = *(const float2*)&rrow[n];
                    o.x = sc * (c0 + addM) + be + rv.x;
                    o.y = sc * (c1 + addM) + be + rv.y;
                }
                *(float2*)&crow[n] = o;
                if constexpr (EPI == 2) {
                    float2 o2 = { o.x * gwv, o.y * gwv };
                    *(float2*)&o2row[n] = o2;
                }
            }
        }
    }
}

// ---------------------------------------------------------------------------
// Weight rounding: dst = tf32(src), float4-vectorized
// ---------------------------------------------------------------------------
__global__ void round_k(const float* __restrict__ src, float* __restrict__ dst, int n4)
{
    const int i = blockIdx.x * blockDim.x + threadIdx.x;
    if (i >= n4) return;
    float4 v = ((const float4*)src)[i];
    v.x = rnd_tf(v.x); v.y = rnd_tf(v.y); v.z = rnd_tf(v.z); v.w = rnd_tf(v.w);
    ((float4*)dst)[i] = v;
}

// ---------------------------------------------------------------------------
// Transpose + tf32 round: src [rows][cols] -> dst [cols][rows], per batch z
// ---------------------------------------------------------------------------
__global__ void transpose_k(const float* __restrict__ src, float* __restrict__ dst,
                            int rows, int cols)
{
    __shared__ float t[32][33];
    const long bo = (long)blockIdx.z * rows * cols;
    const int c0 = blockIdx.x * 32, r0 = blockIdx.y * 32;
    const int tx = threadIdx.x, ty = threadIdx.y;
    #pragma unroll
    for (int i = 0; i < 32; i += 8)
        t[ty + i][tx] = rnd_tf(src[bo + (long)(r0 + ty + i) * cols + c0 + tx]);
    __syncthreads();
    #pragma unroll
    for (int i = 0; i < 32; i += 8)
        dst[bo + (long)(c0 + ty + i) * rows + r0 + tx] = t[tx][ty + i];
}

// ---------------------------------------------------------------------------
// Avg+Max pooling: one warp per (b,c)
// ---------------------------------------------------------------------------
__global__ void pool_k(const float* __restrict__ na, float* __restrict__ pooled)
{
    const int gw = (int)((blockIdx.x * (long)blockDim.x + threadIdx.x) >> 5);
    const int lane = threadIdx.x & 31;
    if (gw >= Bc * C) return;
    const float* p = na + (long)gw * Na;
    float s = 0.f, m = -3.4e38f;
    for (int i = lane; i < Na; i += 32) { float v = p[i]; s += v; m = fmaxf(m, v); }
    #pragma unroll
    for (int o = 16; o; o >>= 1) {
        s += __shfl_xor_sync(0xffffffffu, s, o);
        m = fmaxf(m, __shfl_xor_sync(0xffffffffu, m, o));
    }
    if (lane == 0) {
        const int b = gw / C, c = gw % C;
        pooled[(long)b * 2 * C + c]     = s * (1.f / Na);
        pooled[(long)b * 2 * C + C + c] = m;
    }
}

// ---------------------------------------------------------------------------
// Channel gate MLP + sigmoid, one block per batch
// ---------------------------------------------------------------------------
__global__ void gate_k(const float* __restrict__ pooled,
                       const float* __restrict__ w1, const float* __restrict__ b1,
                       const float* __restrict__ w2, const float* __restrict__ b2,
                       float* __restrict__ cw)
{
    __shared__ float sv[2 * C];
    __shared__ float h[2][R];
    __shared__ float hs[R];
    const int b = blockIdx.x, tid = threadIdx.x;
    for (int i = tid; i < 2 * C; i += blockDim.x)
        sv[i] = pooled[(long)b * 2 * C + i];
    __syncthreads();
    if (tid < 2 * R) {
        const int which = tid / R, r = tid % R;
        const float* v = sv + which * C;
        const float* wr = w1 + r * C;
        float acc = b1[r];
        for (int c = 0; c < C; c++) acc += wr[c] * v[c];
        h[which][r] = fmaxf(acc, 0.f);
    }
    __syncthreads();
    if (tid < R) hs[tid] = h[0][tid] + h[1][tid];
    __syncthreads();
    for (int c = tid; c < C; c += blockDim.x) {
        const float* wc = w2 + c * R;
        float acc = 2.f * b2[c];
        #pragma unroll 8
        for (int r = 0; r < R; r++) acc += wc[r] * hs[r];
        cw[(long)b * C + c] = 1.f / (1.f + expf(-acc));
    }
}

// ---------------------------------------------------------------------------
// Channel scaling (act_aim): dst = src * cw[b*C + c]
// ---------------------------------------------------------------------------
__global__ void scale_k(const float* __restrict__ src, const float* __restrict__ cw,
                        float* __restrict__ dst, int q_div, long total4)
{
    const long i = blockIdx.x * (long)blockDim.x + threadIdx.x;
    if (i >= total4) return;
    const float w = cw[i / q_div];
    float4 v = ((const float4*)src)[i];
    v.x *= w; v.y *= w; v.z *= w; v.w *= w;
    ((float4*)dst)[i] = v;
}

// ---------------------------------------------------------------------------
// Launch  (order arranged so ncu's -s 5 -c 1 profiles G2, a big tgemm)
// ---------------------------------------------------------------------------
extern "C" void kernel_launch(void* const* d_in, const int* in_sizes, int n_in,
                              void* d_out, int out_size)
{
    (void)in_sizes; (void)n_in; (void)out_size;
    const float* detect = (const float*)d_in[0];
    const float* aim    = (const float*)d_in[1];
    const float* g_w    = (const float*)d_in[2];
    const float* g_b    = (const float*)d_in[3];
    const float* th_w   = (const float*)d_in[4];
    const float* th_b   = (const float*)d_in[5];
    const float* ph_w   = (const float*)d_in[6];
    const float* ph_b   = (const float*)d_in[7];
    const float* W_w    = (const float*)d_in[8];
    const float* W_b    = (const float*)d_in[9];
    const float* W_bn_g = (const float*)d_in[10];
    const float* W_bn_b = (const float*)d_in[11];
    const float* Q_w    = (const float*)d_in[12];
    const float* Q_b    = (const float*)d_in[13];
    const float* Q_bn_g = (const float*)d_in[14];
    const float* Q_bn_b = (const float*)d_in[15];
    const float* m1_w   = (const float*)d_in[16];
    const float* m1_b   = (const float*)d_in[17];
    const float* m2_w   = (const float*)d_in[18];
    const float* m2_b   = (const float*)d_in[19];
    float* out = (float*)d_out;

    float *detT, *aimT, *dx, *phx, *ax, *thx, *fm, *fT, *nap, *ndp, *nonaim, *pooled;
    float *gwr, *thwr, *phwr, *Wwr, *Qwr;
    cudaGetSymbolAddress((void**)&detT,   g_detT);
    cudaGetSymbolAddress((void**)&aimT,   g_aimT);
    cudaGetSymbolAddress((void**)&dx,     g_dx);
    cudaGetSymbolAddress((void**)&phx,    g_phx);
    cudaGetSymbolAddress((void**)&ax,     g_ax);
    cudaGetSymbolAddress((void**)&thx,    g_thx);
    cudaGetSymbolAddress((void**)&fm,     g_fm);
    cudaGetSymbolAddress((void**)&fT,     g_fT);
    cudaGetSymbolAddress((void**)&nap,    g_nap);
    cudaGetSymbolAddress((void**)&ndp,    g_ndp);
    cudaGetSymbolAddress((void**)&nonaim, g_nonaim);
    cudaGetSymbolAddress((void**)&pooled, g_pooled);
    cudaGetSymbolAddress((void**)&gwr,    g_gwr);
    cudaGetSymbolAddress((void**)&thwr,   g_thwr);
    cudaGetSymbolAddress((void**)&phwr,   g_phwr);
    cudaGetSymbolAddress((void**)&Wwr,    g_Wwr);
    cudaGetSymbolAddress((void**)&Qwr,    g_Qwr);

    const long offNonDet = 0;
    const long offActDet = (long)Bc * C * Nd;
    const long offActAim = 2 * offActDet;
    const long offCw     = offActAim + (long)Bc * C * Na;

    cudaFuncSetAttribute(tgemm<0,0,1>, cudaFuncAttributeMaxDynamicSharedMemorySize, GSMEM);
    cudaFuncSetAttribute(tgemm<0,1,1>, cudaFuncAttributeMaxDynamicSharedMemorySize, GSMEM);
    cudaFuncSetAttribute(tgemm<0,2,1>, cudaFuncAttributeMaxDynamicSharedMemorySize, GSMEM);
    cudaFuncSetAttribute(tgemm<1,0,0>, cudaFuncAttributeMaxDynamicSharedMemorySize, GSMEM);
    cudaFuncSetAttribute(tgemm<2,0,0>, cudaFuncAttributeMaxDynamicSharedMemorySize, GSMEM);

    const int n4 = (Ci * C) / 4;

    // launches 0-1: transposes (with tf32 rounding)
    transpose_k<<<dim3(Nd / 32, C / 32, Bc), dim3(32, 8)>>>(detect, detT, C, Nd);
    transpose_k<<<dim3(Na / 32, C / 32, Bc), dim3(32, 8)>>>(aim,    aimT, C, Na);
    // launches 2-3: round only the weights G1/G2 need
    round_k<<<(n4 + 255) / 256, 256>>>(g_w,  gwr,  n4);
    round_k<<<(n4 + 255) / 256, 256>>>(ph_w, phwr, n4);

    // launch 4 — G1: d_x[Ci,Nd] = gwr * detT^T + g_b[m]          (rounded out)
    tgemm<0,1,1><<<dim3(Nd/128, Ci/128, Bc), 256, GSMEM>>>(
        gwr, detT, dx, C, Nd, 0, (long)Nd*C, (long)Ci*Nd, 1.f,
        g_b, nullptr, nullptr, nullptr, nullptr, 0, nullptr, nullptr);
    // launch 5 (ncu-profiled) — G2: phi_x[Nd,Ci] = detT * phwr^T + ph_b[n]
    tgemm<0,2,1><<<dim3(Ci/128, Nd/128, Bc), 256, GSMEM>>>(
        detT, phwr, phx, C, Ci, (long)Nd*C, 0, (long)Nd*Ci, 1.f,
        nullptr, ph_b, nullptr, nullptr, nullptr, 0, nullptr, nullptr);

    // remaining weight rounds just-in-time
    round_k<<<(n4 + 255) / 256, 256>>>(th_w, thwr, n4);
    // G3: a_x[Ci,Na] = gwr * aimT^T + g_b[m]          (rounded out)
    tgemm<0,1,1><<<dim3(Na/128, Ci/128, Bc), 256, GSMEM>>>(
        gwr, aimT, ax, C, Na, 0, (long)Na*C, (long)Ci*Na, 1.f,
        g_b, nullptr, nullptr, nullptr, nullptr, 0, nullptr, nullptr);
    // G4: theta_x[Na,Ci] = aimT * thwr^T + th_b[n]    (rounded out)
    tgemm<0,2,1><<<dim3(Ci/128, Na/128, Bc), 256, GSMEM>>>(
        aimT, thwr, thx, C, Ci, (long)Na*C, 0, (long)Na*Ci, 1.f,
        nullptr, th_b, nullptr, nullptr, nullptr, 0, nullptr, nullptr);
    // G5: f[Na,Nd] = theta * phi^T                    (rounded out)
    tgemm<0,0,1><<<dim3(Nd/128, Na/128, Bc), 256, GSMEM>>>(
        thx, phx, fm, Ci, Nd, (long)Na*Ci, (long)Nd*Ci, (long)Na*Nd, 1.f,
        nullptr, nullptr, nullptr, nullptr, nullptr, 0, nullptr, nullptr);
    // G5b: fT[Nd,Na] = phi * theta^T                  (rounded out)
    tgemm<0,0,1><<<dim3(Na/128, Nd/128, Bc), 256, GSMEM>>>(
        phx, thx, fT, Ci, Na, (long)Nd*Ci, (long)Na*Ci, (long)Nd*Na, 1.f,
        nullptr, nullptr, nullptr, nullptr, nullptr, 0, nullptr, nullptr);
    // G6: nap[Na,Ci] = (1/Nd) f * d_x^T               (rounded out)
    tgemm<0,0,1><<<dim3(Ci/128, Na/128, Bc), 256, GSMEM>>>(
        fm, dx, nap, Nd, Ci, (long)Na*Nd, (long)Ci*Nd, (long)Na*Ci, 1.f/Nd,
        nullptr, nullptr, nullptr, nullptr, nullptr, 0, nullptr, nullptr);
    // G7: ndp[Nd,Ci] = (1/Na) fT * a_x^T              (rounded out)
    tgemm<0,0,1><<<dim3(Ci/128, Nd/128, Bc), 256, GSMEM>>>(
        fT, ax, ndp, Na, Ci, (long)Nd*Na, (long)Ci*Na, (long)Nd*Ci, 1.f/Na,
        nullptr, nullptr, nullptr, nullptr, nullptr, 0, nullptr, nullptr);
    // G8: non_aim[C,Na] = bn(Wwr * nap^T + W_b) + aim (full precision out)
    round_k<<<(n4 + 255) / 256, 256>>>(W_w, Wwr, n4);
    tgemm<1,0,0><<<dim3(Na/128, C/128, Bc), 256, GSMEM>>>(
        Wwr, nap, nonaim, Ci, Na, 0, (long)Na*Ci, (long)C*Na, 1.f,
        W_b, nullptr, W_bn_g, W_bn_b, aim, (long)C*Na, nullptr, nullptr);
    // pool + gate
    pool_k<<<(Bc * C) / 8, 256>>>(nonaim, pooled);
    gate_k<<<Bc, 256>>>(pooled, m1_w, m1_b, m2_w, m2_b, out + offCw);
    // G9: non_det[C,Nd] = bn(Qwr * ndp^T + Q_b) + detect ; act_det fused
    round_k<<<(n4 + 255) / 256, 256>>>(Q_w, Qwr, n4);
    tgemm<2,0,0><<<dim3(Nd/128, C/128, Bc), 256, GSMEM>>>(
        Qwr, ndp, out + offNonDet, Ci, Nd, 0, (long)Nd*Ci, (long)C*Nd, 1.f,
        Q_b, nullptr, Q_bn_g, Q_bn_b, detect, (long)C*Nd,
        out + offCw, out + offActDet);
    // act_aim = non_aim * cw
    const long t4a = (long)Bc * C * Na / 4;
    scale_k<<<(unsigned)((t4a + 255) / 256), 256>>>(
        nonaim, out + offCw, out + offActAim, Na / 4, t4a);
}

// round 12
// speedup vs baseline: 1.1321x; 1.1321x over previous
#include <cuda_runtime.h>
#include <cstdint>
#include <math.h>

// ---------------------------------------------------------------------------
// Problem constants
// ---------------------------------------------------------------------------
constexpr int Bc = 8;
constexpr int C  = 1024;
constexpr int Ci = 512;
constexpr int Nd = 48 * 48;          // 2304
constexpr int Na = 16 * 16;          // 256
constexpr int R  = 64;               // C / 16
constexpr float BN_INV = 0.9999950000374997f;  // 1/sqrt(1+1e-5)

// ---------------------------------------------------------------------------
// Device scratch (static)
// ---------------------------------------------------------------------------
__device__ float g_detT  [Bc * Nd * C];    // rounded tf32
__device__ float g_aimT  [Bc * Na * C];    // rounded tf32
__device__ float g_dx    [Bc * Ci * Nd];
__device__ float g_phx   [Bc * Nd * Ci];
__device__ float g_ax    [Bc * Ci * Na];
__device__ float g_thx   [Bc * Na * Ci];
__device__ float g_fm    [Bc * Na * Nd];
__device__ float g_fT    [Bc * Nd * Na];
__device__ float g_nap   [Bc * Na * Ci];
__device__ float g_ndp   [Bc * Nd * Ci];
__device__ float g_nonaim[Bc * C  * Na];
__device__ float g_pooled[Bc * 2  * C];
// rounded weight copies
__device__ float g_gwr [Ci * C];
__device__ float g_thwr[Ci * C];
__device__ float g_phwr[Ci * C];
__device__ float g_Wwr [C * Ci];
__device__ float g_Qwr [C * Ci];

// ---------------------------------------------------------------------------
// helpers
// ---------------------------------------------------------------------------
__device__ __forceinline__ uint32_t f2tf(float x) {
    uint32_t r;
    asm("cvt.rna.tf32.f32 %0, %1;" : "=r"(r) : "f"(x));
    return r;
}
__device__ __forceinline__ float rnd_tf(float x) {
    return __uint_as_float(f2tf(x));
}
__device__ __forceinline__ uint32_t smem_u32(const void* p) {
    uint32_t a;
    asm("{ .reg .u64 t; cvta.to.shared.u64 t, %1; cvt.u32.u64 %0, t; }" : "=r"(a) : "l"(p));
    return a;
}
__device__ __forceinline__ void mma8(float* d, const uint32_t* a, const uint32_t* b) {
    asm volatile(
        "mma.sync.aligned.m16n8k8.row.col.f32.tf32.tf32.f32 "
        "{%0,%1,%2,%3}, {%4,%5,%6,%7}, {%8,%9}, {%0,%1,%2,%3};"
        : "+f"(d[0]), "+f"(d[1]), "+f"(d[2]), "+f"(d[3])
        : "r"(a[0]), "r"(a[1]), "r"(a[2]), "r"(a[3]), "r"(b[0]), "r"(b[1]));
}
__device__ __forceinline__ void ldsm4(uint32_t* r, uint32_t a) {
    asm volatile("ldmatrix.sync.aligned.m8n8.x4.shared.b16 {%0,%1,%2,%3}, [%4];"
        : "=r"(r[0]), "=r"(r[1]), "=r"(r[2]), "=r"(r[3]) : "r"(a));
}
__device__ __forceinline__ void cpa16(uint32_t s, const void* g) {
    asm volatile("cp.async.cg.shared.global [%0], [%1], 16;" :: "r"(s), "l"(g));
}
#define CPA_COMMIT() asm volatile("cp.async.commit_group;" ::: "memory")
#define CPA_WAIT2()  asm volatile("cp.async.wait_group 2;" ::: "memory")

// ---------------------------------------------------------------------------
// tf32 mma.sync GEMM:  D[M,N] = alpha * A[M,K] * B[N,K]^T  (+ epilogue)
//   Template NB = block N tile (128 or 64).
//   NB=128: 256 thr, 8 warps (4m x 2n).  NB=64: 128 thr, 4 warps (4m x 1n).
//   Warp tile always 32x64. BK=16, 4-stage cp.async (R10 committed config).
//   Fragment loads via ldmatrix.x4 (verified bit-exact R10).
//   Inputs MUST be tf32-pre-rounded fp32 (cp.async truncation then exact).
//   Smem k-stride 20 words -> ldmatrix phases conflict-free (R10-verified).
//   Requires M%128==0, N%NB==0, K%16==0, row strides == K.
//   EPI 0: alpha*acc (+ bM[m] if BMODE==1, + bN[n] if BMODE==2)
//          RND=1 -> output rounded to tf32 (GEMM-feeding intermediates)
//   EPI 1: bng[m]*BN_INV*(acc+bM[m]) + bnb[m] + resid[m*ldc+n]
//   EPI 2: EPI1 value v; additionally out2 = v * cw[bz*M + m]
// ---------------------------------------------------------------------------
constexpr int SA   = 20;               // padded k-stride in words (16 + 4)
constexpr int NSTG = 4;

template<int EPI, int BMODE, int RND, int NB>
__global__ void __launch_bounds__(NB * 2, (NB == 128) ? 2 : 3)
tgemm(const float* __restrict__ A, const float* __restrict__ B,
      float* __restrict__ Co,
      int K, int ldc, long strA, long strB, long strC, float alpha,
      const float* __restrict__ bM, const float* __restrict__ bN,
      const float* __restrict__ bng, const float* __restrict__ bnb,
      const float* __restrict__ resid, long sR,
      const float* __restrict__ cw, float* __restrict__ out2)
{
    constexpr int AWw    = 128 * SA;           // words of A per stage
    constexpr int STAGEB = (128 + NB) * SA * 4;

    extern __shared__ uint32_t sm[];
    const uint32_t smb = smem_u32(sm);

    const int tid = threadIdx.x, lane = tid & 31, wid = tid >> 5;
    const int wm = wid & 3, wn = wid >> 2;     // wn in [0, NB/64)
    const int bz = blockIdx.z;
    const int bm = blockIdx.y * 128, bn = blockIdx.x * NB;

    // ---- loader addressing ----
    const float* agp;  uint32_t  asp;          // A side
    const float* bgp;  uint32_t  bsp;          // B side
    if constexpr (NB == 128) {
        // 256 thr: t<128 -> A row t; t>=128 -> B row t-128 (4 cpa16 each)
        const int lrow = tid & 127;
        const bool isA = tid < 128;
        agp = (isA ? A + (long)bz * strA + (long)(bm + lrow) * K
                   : B + (long)bz * strB + (long)(bn + lrow) * K);
        asp = smb + (uint32_t)(((isA ? 0 : AWw) + lrow * SA) * 4);
        bgp = nullptr; bsp = 0;
    } else {
        // 128 thr: A row t (4 cpa16) + B row t/2 k-half (t&1)*8 (2 cpa16)
        agp = A + (long)bz * strA + (long)(bm + tid) * K;
        asp = smb + (uint32_t)((tid * SA) * 4);
        bgp = B + (long)bz * strB + (long)(bn + (tid >> 1)) * K + (tid & 1) * 8;
        bsp = smb + (uint32_t)((AWw + (tid >> 1) * SA + (tid & 1) * 8) * 4);
    }

    auto loadt = [&](int kt, int st) {
        const uint32_t so = (uint32_t)(st * STAGEB);
        const float* gp = agp + kt * 16;
        #pragma unroll
        for (int j = 0; j < 4; j++) cpa16(asp + so + j * 16, gp + j * 4);
        if constexpr (NB == 64) {
            const float* gb = bgp + kt * 16;
            #pragma unroll
            for (int j = 0; j < 2; j++) cpa16(bsp + so + j * 16, gb + j * 4);
        }
    };

    // ldmatrix per-thread base addresses (validated R10):
    // A: row = wm*32 + (lane & 15), colw = 4*(lane >> 4)
    // B: row = wn*64 + (lane & 7) + 8*(lane >> 4), colw = 4*((lane >> 3) & 1)
    const uint32_t aAddr = smb +
        (uint32_t)(((wm * 32 + (lane & 15)) * SA + 4 * (lane >> 4)) * 4);
    const uint32_t bAddr = smb +
        (uint32_t)((AWw + (wn * 64 + (lane & 7) + 8 * (lane >> 4)) * SA
                    + 4 * ((lane >> 3) & 1)) * 4);

    float acc[2][8][4];
    #pragma unroll
    for (int i = 0; i < 2; i++)
        #pragma unroll
        for (int j = 0; j < 8; j++)
            #pragma unroll
            for (int q = 0; q < 4; q++) acc[i][j][q] = 0.f;

    auto compute = [&](int st) {
        const uint32_t stoff = (uint32_t)(st * STAGEB);
        #pragma unroll
        for (int k8 = 0; k8 < 2; k8++) {
            const uint32_t kboff = stoff + (uint32_t)(k8 * 32);   // 8 words
            uint32_t af[2][4];
            ldsm4(af[0], aAddr + kboff);
            ldsm4(af[1], aAddr + kboff + 16 * SA * 4);
            uint32_t bf[4][4];
            #pragma unroll
            for (int p = 0; p < 4; p++)
                ldsm4(bf[p], bAddr + kboff + (uint32_t)(p * 16 * SA * 4));
            #pragma unroll
            for (int ni = 0; ni < 8; ni++) {
                const uint32_t* bb = &bf[ni >> 1][(ni & 1) * 2];
                mma8(acc[0][ni], af[0], bb);
                mma8(acc[1][ni], af[1], bb);
            }
        }
    };

    const int nk = K / 16;          // >= 32 for all GEMMs here
    loadt(0, 0); CPA_COMMIT();
    loadt(1, 1); CPA_COMMIT();
    loadt(2, 2); CPA_COMMIT();

    for (int kt = 0; kt < nk; kt++) {
        const int s = kt & 3;
        CPA_WAIT2();                 // group kt complete (one commit/iter)
        __syncthreads();             // writes visible; prev compute done
        if (kt + 3 < nk) loadt(kt + 3, (kt + 3) & 3);
        CPA_COMMIT();                // commit every iter (possibly empty)
        compute(s);
    }

    // ---- epilogue ----
    const int g = lane >> 2, t2 = (lane & 3) * 2;
    #pragma unroll
    for (int mi = 0; mi < 2; mi++) {
        #pragma unroll
        for (int half = 0; half < 2; half++) {
            const int m = bm + wm * 32 + mi * 16 + half * 8 + g;
            float addM = 0.f, sc = 1.f, be = 0.f, gwv = 0.f;
            if constexpr (EPI == 0) {
                if constexpr (BMODE == 1) addM = bM[m];
            } else {
                addM = bM[m]; sc = bng[m] * BN_INV; be = bnb[m];
            }
            float* crow = Co + (long)bz * strC + (long)m * ldc;
            const float* rrow = nullptr;
            float* o2row = nullptr;
            if constexpr (EPI >= 1) rrow = resid + (long)bz * sR + (long)m * ldc;
            if constexpr (EPI == 2) {
                o2row = out2 + (long)bz * strC + (long)m * ldc;
                gwv = cw[(long)bz * (gridDim.y * 128) + m];
            }
            #pragma unroll
            for (int ni = 0; ni < 8; ni++) {
                const int n = bn + wn * 64 + ni * 8 + t2;
                const float c0 = acc[mi][ni][half * 2 + 0];
                const float c1 = acc[mi][ni][half * 2 + 1];
                float2 o;
                if constexpr (EPI == 0) {
                    o.x = alpha * c0 + addM;
                    o.y = alpha * c1 + addM;
                    if constexpr (BMODE == 2) { o.x += bN[n]; o.y += bN[n + 1]; }
                    if constexpr (RND == 1) { o.x = rnd_tf(o.x); o.y = rnd_tf(o.y); }
                } else {
                    float2 rv = *(const float2*)&rrow[n];
                    o.x = sc * (c0 + addM) + be + rv.x;
                    o.y = sc * (c1 + addM) + be + rv.y;
                }
                *(float2*)&crow[n] = o;
                if constexpr (EPI == 2) {
                    float2 o2 = { o.x * gwv, o.y * gwv };
                    *(float2*)&o2row[n] = o2;
                }
            }
        }
    }
}

constexpr int GS128 = NSTG * (128 + 128) * SA * 4;   // 81920 B
constexpr int GS64  = NSTG * (128 + 64)  * SA * 4;   // 61440 B

// ---------------------------------------------------------------------------
// Merged weight rounding: 5 matrices in one launch (blockIdx.y selects)
// ---------------------------------------------------------------------------
__global__ void round5_k(const float* s0, const float* s1, const float* s2,
                         const float* s3, const float* s4,
                         float* d0, float* d1, float* d2, float* d3, float* d4,
                         int n4)
{
    const float* s; float* d;
    switch (blockIdx.y) {
        case 0:  s = s0; d = d0; break;
        case 1:  s = s1; d = d1; break;
        case 2:  s = s2; d = d2; break;
        case 3:  s = s3; d = d3; break;
        default: s = s4; d = d4; break;
    }
    const int i = blockIdx.x * blockDim.x + threadIdx.x;
    if (i >= n4) return;
    float4 v = ((const float4*)s)[i];
    v.x = rnd_tf(v.x); v.y = rnd_tf(v.y); v.z = rnd_tf(v.z); v.w = rnd_tf(v.w);
    ((float4*)d)[i] = v;
}

// ---------------------------------------------------------------------------
// Transpose + tf32 round: src [rows][cols] -> dst [cols][rows], per batch z
// ---------------------------------------------------------------------------
__global__ void transpose_k(const float* __restrict__ src, float* __restrict__ dst,
                            int rows, int cols)
{
    __shared__ float t[32][33];
    const long bo = (long)blockIdx.z * rows * cols;
    const int c0 = blockIdx.x * 32, r0 = blockIdx.y * 32;
    const int tx = threadIdx.x, ty = threadIdx.y;
    #pragma unroll
    for (int i = 0; i < 32; i += 8)
        t[ty + i][tx] = rnd_tf(src[bo + (long)(r0 + ty + i) * cols + c0 + tx]);
    __syncthreads();
    #pragma unroll
    for (int i = 0; i < 32; i += 8)
        dst[bo + (long)(c0 + ty + i) * rows + r0 + tx] = t[tx][ty + i];
}

// ---------------------------------------------------------------------------
// Avg+Max pooling: one warp per (b,c)
// ---------------------------------------------------------------------------
__global__ void pool_k(const float* __restrict__ na, float* __restrict__ pooled)
{
    const int gw = (int)((blockIdx.x * (long)blockDim.x + threadIdx.x) >> 5);
    const int lane = threadIdx.x & 31;
    if (gw >= Bc * C) return;
    const float* p = na + (long)gw * Na;
    float s = 0.f, m = -3.4e38f;
    for (int i = lane; i < Na; i += 32) { float v = p[i]; s += v; m = fmaxf(m, v); }
    #pragma unroll
    for (int o = 16; o; o >>= 1) {
        s += __shfl_xor_sync(0xffffffffu, s, o);
        m = fmaxf(m, __shfl_xor_sync(0xffffffffu, m, o));
    }
    if (lane == 0) {
        const int b = gw / C, c = gw % C;
        pooled[(long)b * 2 * C + c]     = s * (1.f / Na);
        pooled[(long)b * 2 * C + C + c] = m;
    }
}

// ---------------------------------------------------------------------------
// Channel gate MLP + sigmoid, one block per batch
// ---------------------------------------------------------------------------
__global__ void gate_k(const float* __restrict__ pooled,
                       const float* __restrict__ w1, const float* __restrict__ b1,
                       const float* __restrict__ w2, const float* __restrict__ b2,
                       float* __restrict__ cw)
{
    __shared__ float sv[2 * C];
    __shared__ float h[2][R];
    __shared__ float hs[R];
    const int b = blockIdx.x, tid = threadIdx.x;
    for (int i = tid; i < 2 * C; i += blockDim.x)
        sv[i] = pooled[(long)b * 2 * C + i];
    __syncthreads();
    if (tid < 2 * R) {
        const int which = tid / R, r = tid % R;
        const float* v = sv + which * C;
        const float* wr = w1 + r * C;
        float acc = b1[r];
        for (int c = 0; c < C; c++) acc += wr[c] * v[c];
        h[which][r] = fmaxf(acc, 0.f);
    }
    __syncthreads();
    if (tid < R) hs[tid] = h[0][tid] + h[1][tid];
    __syncthreads();
    for (int c = tid; c < C; c += blockDim.x) {
        const float* wc = w2 + c * R;
        float acc = 2.f * b2[c];
        #pragma unroll 8
        for (int r = 0; r < R; r++) acc += wc[r] * hs[r];
        cw[(long)b * C + c] = 1.f / (1.f + expf(-acc));
    }
}

// ---------------------------------------------------------------------------
// Channel scaling (act_aim): dst = src * cw[b*C + c]
// ---------------------------------------------------------------------------
__global__ void scale_k(const float* __restrict__ src, const float* __restrict__ cw,
                        float* __restrict__ dst, int q_div, long total4)
{
    const long i = blockIdx.x * (long)blockDim.x + threadIdx.x;
    if (i >= total4) return;
    const float w = cw[i / q_div];
    float4 v = ((const float4*)src)[i];
    v.x *= w; v.y *= w; v.z *= w; v.w *= w;
    ((float4*)dst)[i] = v;
}

// ---------------------------------------------------------------------------
// Launch
// ---------------------------------------------------------------------------
extern "C" void kernel_launch(void* const* d_in, const int* in_sizes, int n_in,
                              void* d_out, int out_size)
{
    (void)in_sizes; (void)n_in; (void)out_size;
    const float* detect = (const float*)d_in[0];
    const float* aim    = (const float*)d_in[1];
    const float* g_w    = (const float*)d_in[2];
    const float* g_b    = (const float*)d_in[3];
    const float* th_w   = (const float*)d_in[4];
    const float* th_b   = (const float*)d_in[5];
    const float* ph_w   = (const float*)d_in[6];
    const float* ph_b   = (const float*)d_in[7];
    const float* W_w    = (const float*)d_in[8];
    const float* W_b    = (const float*)d_in[9];
    const float* W_bn_g = (const float*)d_in[10];
    const float* W_bn_b = (const float*)d_in[11];
    const float* Q_w    = (const float*)d_in[12];
    const float* Q_b    = (const float*)d_in[13];
    const float* Q_bn_g = (const float*)d_in[14];
    const float* Q_bn_b = (const float*)d_in[15];
    const float* m1_w   = (const float*)d_in[16];
    const float* m1_b   = (const float*)d_in[17];
    const float* m2_w   = (const float*)d_in[18];
    const float* m2_b   = (const float*)d_in[19];
    float* out = (float*)d_out;

    float *detT, *aimT, *dx, *phx, *ax, *thx, *fm, *fT, *nap, *ndp, *nonaim, *pooled;
    float *gwr, *thwr, *phwr, *Wwr, *Qwr;
    cudaGetSymbolAddress((void**)&detT,   g_detT);
    cudaGetSymbolAddress((void**)&aimT,   g_aimT);
    cudaGetSymbolAddress((void**)&dx,     g_dx);
    cudaGetSymbolAddress((void**)&phx,    g_phx);
    cudaGetSymbolAddress((void**)&ax,     g_ax);
    cudaGetSymbolAddress((void**)&thx,    g_thx);
    cudaGetSymbolAddress((void**)&fm,     g_fm);
    cudaGetSymbolAddress((void**)&fT,     g_fT);
    cudaGetSymbolAddress((void**)&nap,    g_nap);
    cudaGetSymbolAddress((void**)&ndp,    g_ndp);
    cudaGetSymbolAddress((void**)&nonaim, g_nonaim);
    cudaGetSymbolAddress((void**)&pooled, g_pooled);
    cudaGetSymbolAddress((void**)&gwr,    g_gwr);
    cudaGetSymbolAddress((void**)&thwr,   g_thwr);
    cudaGetSymbolAddress((void**)&phwr,   g_phwr);
    cudaGetSymbolAddress((void**)&Wwr,    g_Wwr);
    cudaGetSymbolAddress((void**)&Qwr,    g_Qwr);

    const long offNonDet = 0;
    const long offActDet = (long)Bc * C * Nd;
    const long offActAim = 2 * offActDet;
    const long offCw     = offActAim + (long)Bc * C * Na;

    cudaFuncSetAttribute(tgemm<0,1,1,128>, cudaFuncAttributeMaxDynamicSharedMemorySize, GS128);
    cudaFuncSetAttribute(tgemm<0,2,1,128>, cudaFuncAttributeMaxDynamicSharedMemorySize, GS128);
    cudaFuncSetAttribute(tgemm<0,0,1,128>, cudaFuncAttributeMaxDynamicSharedMemorySize, GS128);
    cudaFuncSetAttribute(tgemm<2,0,0,128>, cudaFuncAttributeMaxDynamicSharedMemorySize, GS128);
    cudaFuncSetAttribute(tgemm<0,1,1,64>,  cudaFuncAttributeMaxDynamicSharedMemorySize, GS64);
    cudaFuncSetAttribute(tgemm<0,2,1,64>,  cudaFuncAttributeMaxDynamicSharedMemorySize, GS64);
    cudaFuncSetAttribute(tgemm<0,0,1,64>,  cudaFuncAttributeMaxDynamicSharedMemorySize, GS64);
    cudaFuncSetAttribute(tgemm<1,0,0,64>,  cudaFuncAttributeMaxDynamicSharedMemorySize, GS64);

    const int n4 = (Ci * C) / 4;

    // prologue: transposes (with tf32 rounding) + merged weight rounding
    transpose_k<<<dim3(Nd / 32, C / 32, Bc), dim3(32, 8)>>>(detect, detT, C, Nd);
    transpose_k<<<dim3(Na / 32, C / 32, Bc), dim3(32, 8)>>>(aim,    aimT, C, Na);
    round5_k<<<dim3((n4 + 255) / 256, 5), 256>>>(
        g_w, th_w, ph_w, W_w, Q_w, gwr, thwr, phwr, Wwr, Qwr, n4);

    // G1: d_x[Ci,Nd] = gwr * detT^T + g_b[m]          (NB=128, 576 CTAs)
    tgemm<0,1,1,128><<<dim3(Nd/128, Ci/128, Bc), 256, GS128>>>(
        gwr, detT, dx, C, Nd, 0, (long)Nd*C, (long)Ci*Nd, 1.f,
        g_b, nullptr, nullptr, nullptr, nullptr, 0, nullptr, nullptr);
    // G2: phi_x[Nd,Ci] = detT * phwr^T + ph_b[n]      (NB=128, 576)
    tgemm<0,2,1,128><<<dim3(Ci/128, Nd/128, Bc), 256, GS128>>>(
        detT, phwr, phx, C, Ci, (long)Nd*C, 0, (long)Nd*Ci, 1.f,
        nullptr, ph_b, nullptr, nullptr, nullptr, 0, nullptr, nullptr);
    // G3: a_x[Ci,Na] = gwr * aimT^T + g_b[m]          (NB=64, 128 CTAs)
    tgemm<0,1,1,64><<<dim3(Na/64, Ci/128, Bc), 128, GS64>>>(
        gwr, aimT, ax, C, Na, 0, (long)Na*C, (long)Ci*Na, 1.f,
        g_b, nullptr, nullptr, nullptr, nullptr, 0, nullptr, nullptr);
    // G4: theta_x[Na,Ci] = aimT * thwr^T + th_b[n]    (NB=64, 128)
    tgemm<0,2,1,64><<<dim3(Ci/64, Na/128, Bc), 128, GS64>>>(
        aimT, thwr, thx, C, Ci, (long)Na*C, 0, (long)Na*Ci, 1.f,
        nullptr, th_b, nullptr, nullptr, nullptr, 0, nullptr, nullptr);
    // G5: f[Na,Nd] = theta * phi^T                    (NB=128, 288)
    tgemm<0,0,1,128><<<dim3(Nd/128, Na/128, Bc), 256, GS128>>>(
        thx, phx, fm, Ci, Nd, (long)Na*Ci, (long)Nd*Ci, (long)Na*Nd, 1.f,
        nullptr, nullptr, nullptr, nullptr, nullptr, 0, nullptr, nullptr);
    // G5b: fT[Nd,Na] = phi * theta^T                  (NB=128, 288)
    tgemm<0,0,1,128><<<dim3(Na/128, Nd/128, Bc), 256, GS128>>>(
        phx, thx, fT, Ci, Na, (long)Nd*Ci, (long)Na*Ci, (long)Nd*Na, 1.f,
        nullptr, nullptr, nullptr, nullptr, nullptr, 0, nullptr, nullptr);
    // G6: nap[Na,Ci] = (1/Nd) f * d_x^T               (NB=64, 128)
    tgemm<0,0,1,64><<<dim3(Ci/64, Na/128, Bc), 128, GS64>>>(
        fm, dx, nap, Nd, Ci, (long)Na*Nd, (long)Ci*Nd, (long)Na*Ci, 1.f/Nd,
        nullptr, nullptr, nullptr, nullptr, nullptr, 0, nullptr, nullptr);
    // G7: ndp[Nd,Ci] = (1/Na) fT * a_x^T              (NB=128, 576)
    tgemm<0,0,1,128><<<dim3(Ci/128, Nd/128, Bc), 256, GS128>>>(
        fT, ax, ndp, Na, Ci, (long)Nd*Na, (long)Ci*Na, (long)Nd*Ci, 1.f/Na,
        nullptr, nullptr, nullptr, nullptr, nullptr, 0, nullptr, nullptr);
    // G8: non_aim[C,Na] = bn(Wwr * nap^T + W_b) + aim (NB=64, 256)
    tgemm<1,0,0,64><<<dim3(Na/64, C/128, Bc), 128, GS64>>>(
        Wwr, nap, nonaim, Ci, Na, 0, (long)Na*Ci, (long)C*Na, 1.f,
        W_b, nullptr, W_bn_g, W_bn_b, aim, (long)C*Na, nullptr, nullptr);
    // pool + gate
    pool_k<<<(Bc * C) / 8, 256>>>(nonaim, pooled);
    gate_k<<<Bc, 256>>>(pooled, m1_w, m1_b, m2_w, m2_b, out + offCw);
    // G9: non_det[C,Nd] = bn(Qwr * ndp^T + Q_b) + detect ; act_det fused
    tgemm<2,0,0,128><<<dim3(Nd/128, C/128, Bc), 256, GS128>>>(
        Qwr, ndp, out + offNonDet, Ci, Nd, 0, (long)Nd*Ci, (long)C*Nd, 1.f,
        Q_b, nullptr, Q_bn_g, Q_bn_b, detect, (long)C*Nd,
        out + offCw, out + offActDet);
    // act_aim = non_aim * cw
    const long t4a = (long)Bc * C * Na / 4;
    scale_k<<<(unsigned)((t4a + 255) / 256), 256>>>(
        nonaim, out + offCw, out + offActAim, Na / 4, t4a);
}

// round 13
// speedup vs baseline: 1.1794x; 1.0418x over previous
#include <cuda_runtime.h>
#include <cstdint>
#include <math.h>

// ---------------------------------------------------------------------------
// Problem constants
// ---------------------------------------------------------------------------
constexpr int Bc = 8;
constexpr int C  = 1024;
constexpr int Ci = 512;
constexpr int Nd = 48 * 48;          // 2304
constexpr int Na = 16 * 16;          // 256
constexpr int R  = 64;               // C / 16
constexpr float BN_INV = 0.9999950000374997f;  // 1/sqrt(1+1e-5)

// ---------------------------------------------------------------------------
// Device scratch (static)
// ---------------------------------------------------------------------------
__device__ float g_detT  [Bc * Nd * C];    // rounded tf32
__device__ float g_aimT  [Bc * Na * C];    // rounded tf32
__device__ float g_dx    [Bc * Ci * Nd];
__device__ float g_phx   [Bc * Nd * Ci];
__device__ float g_ax    [Bc * Ci * Na];
__device__ float g_thx   [Bc * Na * Ci];
__device__ float g_fm    [Bc * Na * Nd];
__device__ float g_fT    [Bc * Nd * Na];
__device__ float g_nap   [Bc * Na * Ci];
__device__ float g_ndp   [Bc * Nd * Ci];
__device__ float g_nonaim[Bc * C  * Na];
__device__ float g_pooled[Bc * 2  * C];
// rounded weight copies
__device__ float g_gwr [Ci * C];
__device__ float g_thwr[Ci * C];
__device__ float g_phwr[Ci * C];
__device__ float g_Wwr [C * Ci];
__device__ float g_Qwr [C * Ci];

// ---------------------------------------------------------------------------
// helpers
// ---------------------------------------------------------------------------
__device__ __forceinline__ uint32_t f2tf(float x) {
    uint32_t r;
    asm("cvt.rna.tf32.f32 %0, %1;" : "=r"(r) : "f"(x));
    return r;
}
__device__ __forceinline__ float rnd_tf(float x) {
    return __uint_as_float(f2tf(x));
}
__device__ __forceinline__ uint32_t smem_u32(const void* p) {
    uint32_t a;
    asm("{ .reg .u64 t; cvta.to.shared.u64 t, %1; cvt.u32.u64 %0, t; }" : "=r"(a) : "l"(p));
    return a;
}
__device__ __forceinline__ void mma8(float* d, const uint32_t* a, const uint32_t* b) {
    asm volatile(
        "mma.sync.aligned.m16n8k8.row.col.f32.tf32.tf32.f32 "
        "{%0,%1,%2,%3}, {%4,%5,%6,%7}, {%8,%9}, {%0,%1,%2,%3};"
        : "+f"(d[0]), "+f"(d[1]), "+f"(d[2]), "+f"(d[3])
        : "r"(a[0]), "r"(a[1]), "r"(a[2]), "r"(a[3]), "r"(b[0]), "r"(b[1]));
}
__device__ __forceinline__ void ldsm4(uint32_t* r, uint32_t a) {
    asm volatile("ldmatrix.sync.aligned.m8n8.x4.shared.b16 {%0,%1,%2,%3}, [%4];"
        : "=r"(r[0]), "=r"(r[1]), "=r"(r[2]), "=r"(r[3]) : "r"(a));
}
__device__ __forceinline__ void cpa16(uint32_t s, const void* g) {
    asm volatile("cp.async.cg.shared.global [%0], [%1], 16;" :: "r"(s), "l"(g));
}
#define CPA_COMMIT() asm volatile("cp.async.commit_group;" ::: "memory")
#define CPA_WAIT2()  asm volatile("cp.async.wait_group 2;" ::: "memory")

// ---------------------------------------------------------------------------
// tf32 mma.sync GEMM:  D[M,N] = alpha * A[M,K] * B[N,K]^T  (+ epilogue)
//   Template NB = block N tile (128 or 64).
//   NB=128: 256 thr, 8 warps (4m x 2n).  NB=64: 128 thr, 4 warps (4m x 1n).
//   Warp tile always 32x64. BK=16, 4-stage cp.async (committed R10 config).
//   Fragment loads via ldmatrix.x4 (verified bit-exact R10).
//   Inputs MUST be tf32-pre-rounded fp32 (cp.async truncation then exact).
//   Smem k-stride 20 words -> ldmatrix phases conflict-free (R10-verified).
//   Requires M%128==0, N%NB==0, K%16==0, row strides == K.
//   EPI 0: alpha*acc (+ bM[m] if BMODE==1, + bN[n] if BMODE==2)
//          RND=1 -> output rounded to tf32 (GEMM-feeding intermediates)
//   EPI 1: bng[m]*BN_INV*(acc+bM[m]) + bnb[m] + resid[m*ldc+n]
//   EPI 2: EPI1 value v; additionally out2 = v * cw[bz*M + m]
// ---------------------------------------------------------------------------
constexpr int SA   = 20;               // padded k-stride in words (16 + 4)
constexpr int NSTG = 4;

template<int EPI, int BMODE, int RND, int NB>
__global__ void __launch_bounds__(NB * 2, (NB == 128) ? 2 : 3)
tgemm(const float* __restrict__ A, const float* __restrict__ B,
      float* __restrict__ Co,
      int K, int ldc, long strA, long strB, long strC, float alpha,
      const float* __restrict__ bM, const float* __restrict__ bN,
      const float* __restrict__ bng, const float* __restrict__ bnb,
      const float* __restrict__ resid, long sR,
      const float* __restrict__ cw, float* __restrict__ out2)
{
    constexpr int AWw    = 128 * SA;           // words of A per stage
    constexpr int STAGEB = (128 + NB) * SA * 4;

    extern __shared__ uint32_t sm[];
    const uint32_t smb = smem_u32(sm);

    const int tid = threadIdx.x, lane = tid & 31, wid = tid >> 5;
    const int wm = wid & 3, wn = wid >> 2;     // wn in [0, NB/64)
    const int bz = blockIdx.z;
    const int bm = blockIdx.y * 128, bn = blockIdx.x * NB;

    // ---- loader addressing ----
    const float* agp;  uint32_t  asp;          // A side
    const float* bgp;  uint32_t  bsp;          // B side
    if constexpr (NB == 128) {
        const int lrow = tid & 127;
        const bool isA = tid < 128;
        agp = (isA ? A + (long)bz * strA + (long)(bm + lrow) * K
                   : B + (long)bz * strB + (long)(bn + lrow) * K);
        asp = smb + (uint32_t)(((isA ? 0 : AWw) + lrow * SA) * 4);
        bgp = nullptr; bsp = 0;
    } else {
        agp = A + (long)bz * strA + (long)(bm + tid) * K;
        asp = smb + (uint32_t)((tid * SA) * 4);
        bgp = B + (long)bz * strB + (long)(bn + (tid >> 1)) * K + (tid & 1) * 8;
        bsp = smb + (uint32_t)((AWw + (tid >> 1) * SA + (tid & 1) * 8) * 4);
    }

    auto loadt = [&](int kt, int st) {
        const uint32_t so = (uint32_t)(st * STAGEB);
        const float* gp = agp + kt * 16;
        #pragma unroll
        for (int j = 0; j < 4; j++) cpa16(asp + so + j * 16, gp + j * 4);
        if constexpr (NB == 64) {
            const float* gb = bgp + kt * 16;
            #pragma unroll
            for (int j = 0; j < 2; j++) cpa16(bsp + so + j * 16, gb + j * 4);
        }
    };

    // ldmatrix per-thread base addresses (validated R10)
    const uint32_t aAddr = smb +
        (uint32_t)(((wm * 32 + (lane & 15)) * SA + 4 * (lane >> 4)) * 4);
    const uint32_t bAddr = smb +
        (uint32_t)((AWw + (wn * 64 + (lane & 7) + 8 * (lane >> 4)) * SA
                    + 4 * ((lane >> 3) & 1)) * 4);

    float acc[2][8][4];
    #pragma unroll
    for (int i = 0; i < 2; i++)
        #pragma unroll
        for (int j = 0; j < 8; j++)
            #pragma unroll
            for (int q = 0; q < 4; q++) acc[i][j][q] = 0.f;

    auto compute = [&](int st) {
        const uint32_t stoff = (uint32_t)(st * STAGEB);
        #pragma unroll
        for (int k8 = 0; k8 < 2; k8++) {
            const uint32_t kboff = stoff + (uint32_t)(k8 * 32);   // 8 words
            uint32_t af[2][4];
            ldsm4(af[0], aAddr + kboff);
            ldsm4(af[1], aAddr + kboff + 16 * SA * 4);
            uint32_t bf[4][4];
            #pragma unroll
            for (int p = 0; p < 4; p++)
                ldsm4(bf[p], bAddr + kboff + (uint32_t)(p * 16 * SA * 4));
            #pragma unroll
            for (int ni = 0; ni < 8; ni++) {
                const uint32_t* bb = &bf[ni >> 1][(ni & 1) * 2];
                mma8(acc[0][ni], af[0], bb);
                mma8(acc[1][ni], af[1], bb);
            }
        }
    };

    const int nk = K / 16;          // >= 16 for all GEMMs here
    loadt(0, 0); CPA_COMMIT();
    loadt(1, 1); CPA_COMMIT();
    loadt(2, 2); CPA_COMMIT();

    for (int kt = 0; kt < nk; kt++) {
        const int s = kt & 3;
        CPA_WAIT2();                 // group kt complete (one commit/iter)
        __syncthreads();             // writes visible; prev compute done
        if (kt + 3 < nk) loadt(kt + 3, (kt + 3) & 3);
        CPA_COMMIT();                // commit every iter (possibly empty)
        compute(s);
    }

    // ---- epilogue ----
    const int g = lane >> 2, t2 = (lane & 3) * 2;
    #pragma unroll
    for (int mi = 0; mi < 2; mi++) {
        #pragma unroll
        for (int half = 0; half < 2; half++) {
            const int m = bm + wm * 32 + mi * 16 + half * 8 + g;
            float addM = 0.f, sc = 1.f, be = 0.f, gwv = 0.f;
            if constexpr (EPI == 0) {
                if constexpr (BMODE == 1) addM = bM[m];
            } else {
                addM = bM[m]; sc = bng[m] * BN_INV; be = bnb[m];
            }
            float* crow = Co + (long)bz * strC + (long)m * ldc;
            const float* rrow = nullptr;
            float* o2row = nullptr;
            if constexpr (EPI >= 1) rrow = resid + (long)bz * sR + (long)m * ldc;
            if constexpr (EPI == 2) {
                o2row = out2 + (long)bz * strC + (long)m * ldc;
                gwv = cw[(long)bz * (gridDim.y * 128) + m];
            }
            #pragma unroll
            for (int ni = 0; ni < 8; ni++) {
                const int n = bn + wn * 64 + ni * 8 + t2;
                const float c0 = acc[mi][ni][half * 2 + 0];
                const float c1 = acc[mi][ni][half * 2 + 1];
                float2 o;
                if constexpr (EPI == 0) {
                    o.x = alpha * c0 + addM;
                    o.y = alpha * c1 + addM;
                    if constexpr (BMODE == 2) { o.x += bN[n]; o.y += bN[n + 1]; }
                    if constexpr (RND == 1) { o.x = rnd_tf(o.x); o.y = rnd_tf(o.y); }
                } else {
                    float2 rv = *(const float2*)&rrow[n];
                    o.x = sc * (c0 + addM) + be + rv.x;
                    o.y = sc * (c1 + addM) + be + rv.y;
                }
                *(float2*)&crow[n] = o;
                if constexpr (EPI == 2) {
                    float2 o2 = { o.x * gwv, o.y * gwv };
                    *(float2*)&o2row[n] = o2;
                }
            }
        }
    }
}

constexpr int GS128 = NSTG * (128 + 128) * SA * 4;   // 81920 B
constexpr int GS64  = NSTG * (128 + 64)  * SA * 4;   // 61440 B

// ---------------------------------------------------------------------------
// Merged weight rounding: 5 matrices in one launch (blockIdx.y selects)
// ---------------------------------------------------------------------------
__global__ void round5_k(const float* s0, const float* s1, const float* s2,
                         const float* s3, const float* s4,
                         float* d0, float* d1, float* d2, float* d3, float* d4,
                         int n4)
{
    const float* s; float* d;
    switch (blockIdx.y) {
        case 0:  s = s0; d = d0; break;
        case 1:  s = s1; d = d1; break;
        case 2:  s = s2; d = d2; break;
        case 3:  s = s3; d = d3; break;
        default: s = s4; d = d4; break;
    }
    const int i = blockIdx.x * blockDim.x + threadIdx.x;
    if (i >= n4) return;
    float4 v = ((const float4*)s)[i];
    v.x = rnd_tf(v.x); v.y = rnd_tf(v.y); v.z = rnd_tf(v.z); v.w = rnd_tf(v.w);
    ((float4*)d)[i] = v;
}

// ---------------------------------------------------------------------------
// Transpose + tf32 round: src [rows][cols] -> dst [cols][rows], per batch z
// (rnd_tf is idempotent, so safe on already-rounded data, e.g. fm -> fT)
// ---------------------------------------------------------------------------
__global__ void transpose_k(const float* __restrict__ src, float* __restrict__ dst,
                            int rows, int cols)
{
    __shared__ float t[32][33];
    const long bo = (long)blockIdx.z * rows * cols;
    const int c0 = blockIdx.x * 32, r0 = blockIdx.y * 32;
    const int tx = threadIdx.x, ty = threadIdx.y;
    #pragma unroll
    for (int i = 0; i < 32; i += 8)
        t[ty + i][tx] = rnd_tf(src[bo + (long)(r0 + ty + i) * cols + c0 + tx]);
    __syncthreads();
    #pragma unroll
    for (int i = 0; i < 32; i += 8)
        dst[bo + (long)(c0 + ty + i) * rows + r0 + tx] = t[tx][ty + i];
}

// ---------------------------------------------------------------------------
// Avg+Max pooling: one warp per (b,c)
// ---------------------------------------------------------------------------
__global__ void pool_k(const float* __restrict__ na, float* __restrict__ pooled)
{
    const int gw = (int)((blockIdx.x * (long)blockDim.x + threadIdx.x) >> 5);
    const int lane = threadIdx.x & 31;
    if (gw >= Bc * C) return;
    const float* p = na + (long)gw * Na;
    float s = 0.f, m = -3.4e38f;
    for (int i = lane; i < Na; i += 32) { float v = p[i]; s += v; m = fmaxf(m, v); }
    #pragma unroll
    for (int o = 16; o; o >>= 1) {
        s += __shfl_xor_sync(0xffffffffu, s, o);
        m = fmaxf(m, __shfl_xor_sync(0xffffffffu, m, o));
    }
    if (lane == 0) {
        const int b = gw / C, c = gw % C;
        pooled[(long)b * 2 * C + c]     = s * (1.f / Na);
        pooled[(long)b * 2 * C + C + c] = m;
    }
}

// ---------------------------------------------------------------------------
// Channel gate MLP + sigmoid, one block per batch
// ---------------------------------------------------------------------------
__global__ void gate_k(const float* __restrict__ pooled,
                       const float* __restrict__ w1, const float* __restrict__ b1,
                       const float* __restrict__ w2, const float* __restrict__ b2,
                       float* __restrict__ cw)
{
    __shared__ float sv[2 * C];
    __shared__ float h[2][R];
    __shared__ float hs[R];
    const int b = blockIdx.x, tid = threadIdx.x;
    for (int i = tid; i < 2 * C; i += blockDim.x)
        sv[i] = pooled[(long)b * 2 * C + i];
    __syncthreads();
    if (tid < 2 * R) {
        const int which = tid / R, r = tid % R;
        const float* v = sv + which * C;
        const float* wr = w1 + r * C;
        float acc = b1[r];
        for (int c = 0; c < C; c++) acc += wr[c] * v[c];
        h[which][r] = fmaxf(acc, 0.f);
    }
    __syncthreads();
    if (tid < R) hs[tid] = h[0][tid] + h[1][tid];
    __syncthreads();
    for (int c = tid; c < C; c += blockDim.x) {
        const float* wc = w2 + c * R;
        float acc = 2.f * b2[c];
        #pragma unroll 8
        for (int r = 0; r < R; r++) acc += wc[r] * hs[r];
        cw[(long)b * C + c] = 1.f / (1.f + expf(-acc));
    }
}

// ---------------------------------------------------------------------------
// Channel scaling (act_aim): dst = src * cw[b*C + c]
// ---------------------------------------------------------------------------
__global__ void scale_k(const float* __restrict__ src, const float* __restrict__ cw,
                        float* __restrict__ dst, int q_div, long total4)
{
    const long i = blockIdx.x * (long)blockDim.x + threadIdx.x;
    if (i >= total4) return;
    const float w = cw[i / q_div];
    float4 v = ((const float4*)src)[i];
    v.x *= w; v.y *= w; v.z *= w; v.w *= w;
    ((float4*)dst)[i] = v;
}

// ---------------------------------------------------------------------------
// Launch
// ---------------------------------------------------------------------------
extern "C" void kernel_launch(void* const* d_in, const int* in_sizes, int n_in,
                              void* d_out, int out_size)
{
    (void)in_sizes; (void)n_in; (void)out_size;
    const float* detect = (const float*)d_in[0];
    const float* aim    = (const float*)d_in[1];
    const float* g_w    = (const float*)d_in[2];
    const float* g_b    = (const float*)d_in[3];
    const float* th_w   = (const float*)d_in[4];
    const float* th_b   = (const float*)d_in[5];
    const float* ph_w   = (const float*)d_in[6];
    const float* ph_b   = (const float*)d_in[7];
    const float* W_w    = (const float*)d_in[8];
    const float* W_b    = (const float*)d_in[9];
    const float* W_bn_g = (const float*)d_in[10];
    const float* W_bn_b = (const float*)d_in[11];
    const float* Q_w    = (const float*)d_in[12];
    const float* Q_b    = (const float*)d_in[13];
    const float* Q_bn_g = (const float*)d_in[14];
    const float* Q_bn_b = (const float*)d_in[15];
    const float* m1_w   = (const float*)d_in[16];
    const float* m1_b   = (const float*)d_in[17];
    const float* m2_w   = (const float*)d_in[18];
    const float* m2_b   = (const float*)d_in[19];
    float* out = (float*)d_out;

    float *detT, *aimT, *dx, *phx, *ax, *thx, *fm, *fT, *nap, *ndp, *nonaim, *pooled;
    float *gwr, *thwr, *phwr, *Wwr, *Qwr;
    cudaGetSymbolAddress((void**)&detT,   g_detT);
    cudaGetSymbolAddress((void**)&aimT,   g_aimT);
    cudaGetSymbolAddress((void**)&dx,     g_dx);
    cudaGetSymbolAddress((void**)&phx,    g_phx);
    cudaGetSymbolAddress((void**)&ax,     g_ax);
    cudaGetSymbolAddress((void**)&thx,    g_thx);
    cudaGetSymbolAddress((void**)&fm,     g_fm);
    cudaGetSymbolAddress((void**)&fT,     g_fT);
    cudaGetSymbolAddress((void**)&nap,    g_nap);
    cudaGetSymbolAddress((void**)&ndp,    g_ndp);
    cudaGetSymbolAddress((void**)&nonaim, g_nonaim);
    cudaGetSymbolAddress((void**)&pooled, g_pooled);
    cudaGetSymbolAddress((void**)&gwr,    g_gwr);
    cudaGetSymbolAddress((void**)&thwr,   g_thwr);
    cudaGetSymbolAddress((void**)&phwr,   g_phwr);
    cudaGetSymbolAddress((void**)&Wwr,    g_Wwr);
    cudaGetSymbolAddress((void**)&Qwr,    g_Qwr);

    const long offNonDet = 0;
    const long offActDet = (long)Bc * C * Nd;
    const long offActAim = 2 * offActDet;
    const long offCw     = offActAim + (long)Bc * C * Na;

    cudaFuncSetAttribute(tgemm<0,1,1,128>, cudaFuncAttributeMaxDynamicSharedMemorySize, GS128);
    cudaFuncSetAttribute(tgemm<0,2,1,128>, cudaFuncAttributeMaxDynamicSharedMemorySize, GS128);
    cudaFuncSetAttribute(tgemm<0,0,1,128>, cudaFuncAttributeMaxDynamicSharedMemorySize, GS128);
    cudaFuncSetAttribute(tgemm<2,0,0,128>, cudaFuncAttributeMaxDynamicSharedMemorySize, GS128);
    cudaFuncSetAttribute(tgemm<0,1,1,64>,  cudaFuncAttributeMaxDynamicSharedMemorySize, GS64);
    cudaFuncSetAttribute(tgemm<0,2,1,64>,  cudaFuncAttributeMaxDynamicSharedMemorySize, GS64);
    cudaFuncSetAttribute(tgemm<0,0,1,64>,  cudaFuncAttributeMaxDynamicSharedMemorySize, GS64);
    cudaFuncSetAttribute(tgemm<1,0,0,64>,  cudaFuncAttributeMaxDynamicSharedMemorySize, GS64);

    const int n4 = (Ci * C) / 4;

    // prologue: transposes (with tf32 rounding) + merged weight rounding
    transpose_k<<<dim3(Nd / 32, C / 32, Bc), dim3(32, 8)>>>(detect, detT, C, Nd);
    transpose_k<<<dim3(Na / 32, C / 32, Bc), dim3(32, 8)>>>(aim,    aimT, C, Na);
    round5_k<<<dim3((n4 + 255) / 256, 5), 256>>>(
        g_w, th_w, ph_w, W_w, Q_w, gwr, thwr, phwr, Wwr, Qwr, n4);

    // G1: d_x[Ci,Nd] = gwr * detT^T + g_b[m]          (NB=128, 576 CTAs)
    tgemm<0,1,1,128><<<dim3(Nd/128, Ci/128, Bc), 256, GS128>>>(
        gwr, detT, dx, C, Nd, 0, (long)Nd*C, (long)Ci*Nd, 1.f,
        g_b, nullptr, nullptr, nullptr, nullptr, 0, nullptr, nullptr);
    // G2: phi_x[Nd,Ci] = detT * phwr^T + ph_b[n]      (NB=128, 576)
    tgemm<0,2,1,128><<<dim3(Ci/128, Nd/128, Bc), 256, GS128>>>(
        detT, phwr, phx, C, Ci, (long)Nd*C, 0, (long)Nd*Ci, 1.f,
        nullptr, ph_b, nullptr, nullptr, nullptr, 0, nullptr, nullptr);
    // G3: a_x[Ci,Na] = gwr * aimT^T + g_b[m]          (NB=64, 128 CTAs)
    tgemm<0,1,1,64><<<dim3(Na/64, Ci/128, Bc), 128, GS64>>>(
        gwr, aimT, ax, C, Na, 0, (long)Na*C, (long)Ci*Na, 1.f,
        g_b, nullptr, nullptr, nullptr, nullptr, 0, nullptr, nullptr);
    // G4: theta_x[Na,Ci] = aimT * thwr^T + th_b[n]    (NB=64, 128)
    tgemm<0,2,1,64><<<dim3(Ci/64, Na/128, Bc), 128, GS64>>>(
        aimT, thwr, thx, C, Ci, (long)Na*C, 0, (long)Na*Ci, 1.f,
        nullptr, th_b, nullptr, nullptr, nullptr, 0, nullptr, nullptr);
    // G5: f[Na,Nd] = theta * phi^T                    (NB=128, 288)
    tgemm<0,0,1,128><<<dim3(Nd/128, Na/128, Bc), 256, GS128>>>(
        thx, phx, fm, Ci, Nd, (long)Na*Ci, (long)Nd*Ci, (long)Na*Nd, 1.f,
        nullptr, nullptr, nullptr, nullptr, nullptr, 0, nullptr, nullptr);
    // T5b: fT[Nd,Na] = transpose(f)  (replaces the G5b GEMM; bit-identical)
    transpose_k<<<dim3(Nd / 32, Na / 32, Bc), dim3(32, 8)>>>(fm, fT, Na, Nd);
    // G6: nap[Na,Ci] = (1/Nd) f * d_x^T               (NB=64, 128)
    tgemm<0,0,1,64><<<dim3(Ci/64, Na/128, Bc), 128, GS64>>>(
        fm, dx, nap, Nd, Ci, (long)Na*Nd, (long)Ci*Nd, (long)Na*Ci, 1.f/Nd,
        nullptr, nullptr, nullptr, nullptr, nullptr, 0, nullptr, nullptr);
    // G7: ndp[Nd,Ci] = (1/Na) fT * a_x^T              (NB=128, 576)
    tgemm<0,0,1,128><<<dim3(Ci/128, Nd/128, Bc), 256, GS128>>>(
        fT, ax, ndp, Na, Ci, (long)Nd*Na, (long)Ci*Na, (long)Nd*Ci, 1.f/Na,
        nullptr, nullptr, nullptr, nullptr, nullptr, 0, nullptr, nullptr);
    // G8: non_aim[C,Na] = bn(Wwr * nap^T + W_b) + aim (NB=64, 256)
    tgemm<1,0,0,64><<<dim3(Na/64, C/128, Bc), 128, GS64>>>(
        Wwr, nap, nonaim, Ci, Na, 0, (long)Na*Ci, (long)C*Na, 1.f,
        W_b, nullptr, W_bn_g, W_bn_b, aim, (long)C*Na, nullptr, nullptr);
    // pool + gate
    pool_k<<<(Bc * C) / 8, 256>>>(nonaim, pooled);
    gate_k<<<Bc, 256>>>(pooled, m1_w, m1_b, m2_w, m2_b, out + offCw);
    // G9: non_det[C,Nd] = bn(Qwr * ndp^T + Q_b) + detect ; act_det fused
    tgemm<2,0,0,128><<<dim3(Nd/128, C/128, Bc), 256, GS128>>>(
        Qwr, ndp, out + offNonDet, Ci, Nd, 0, (long)Nd*Ci, (long)C*Nd, 1.f,
        Q_b, nullptr, Q_bn_g, Q_bn_b, detect, (long)C*Nd,
        out + offCw, out + offActDet);
    // act_aim = non_aim * cw
    const long t4a = (long)Bc * C * Na / 4;
    scale_k<<<(unsigned)((t4a + 255) / 256), 256>>>(
        nonaim, out + offCw, out + offActAim, Na / 4, t4a);
}

// round 14
// speedup vs baseline: 1.9777x; 1.6768x over previous
#include <cuda_runtime.h>
#include <cuda_fp16.h>
#include <cstdint>
#include <math.h>

// ---------------------------------------------------------------------------
// Problem constants
// ---------------------------------------------------------------------------
constexpr int Bc = 8;
constexpr int C  = 1024;
constexpr int Ci = 512;
constexpr int Nd = 48 * 48;          // 2304
constexpr int Na = 16 * 16;          // 256
constexpr int R  = 64;               // C / 16
constexpr float BN_INV = 0.9999950000374997f;  // 1/sqrt(1+1e-5)

// ---------------------------------------------------------------------------
// Device scratch (static). GEMM operands in fp16 (e5m10: same 10-bit
// mantissa as tf32 -> same error model; range checked: |f|<~50, |nap|>~1e-2).
// ---------------------------------------------------------------------------
__device__ __half g_detT  [Bc * Nd * C];
__device__ __half g_aimT  [Bc * Na * C];
__device__ __half g_dx    [Bc * Ci * Nd];
__device__ __half g_phx   [Bc * Nd * Ci];
__device__ __half g_ax    [Bc * Ci * Na];
__device__ __half g_thx   [Bc * Na * Ci];
__device__ __half g_fm    [Bc * Na * Nd];
__device__ __half g_fT    [Bc * Nd * Na];
__device__ __half g_nap   [Bc * Na * Ci];
__device__ __half g_ndp   [Bc * Nd * Ci];
__device__ float  g_nonaim[Bc * C  * Na];      // fp32: feeds pool/scale
__device__ float  g_pooled[Bc * 2  * C];
__device__ __half g_gwr [Ci * C];
__device__ __half g_thwr[Ci * C];
__device__ __half g_phwr[Ci * C];
__device__ __half g_Wwr [C * Ci];
__device__ __half g_Qwr [C * Ci];

// ---------------------------------------------------------------------------
// helpers
// ---------------------------------------------------------------------------
__device__ __forceinline__ uint32_t smem_u32(const void* p) {
    uint32_t a;
    asm("{ .reg .u64 t; cvta.to.shared.u64 t, %1; cvt.u32.u64 %0, t; }" : "=r"(a) : "l"(p));
    return a;
}
__device__ __forceinline__ void mma16(float* d, const uint32_t* a, const uint32_t* b) {
    asm volatile(
        "mma.sync.aligned.m16n8k16.row.col.f32.f16.f16.f32 "
        "{%0,%1,%2,%3}, {%4,%5,%6,%7}, {%8,%9}, {%0,%1,%2,%3};"
        : "+f"(d[0]), "+f"(d[1]), "+f"(d[2]), "+f"(d[3])
        : "r"(a[0]), "r"(a[1]), "r"(a[2]), "r"(a[3]), "r"(b[0]), "r"(b[1]));
}
__device__ __forceinline__ void ldsm4(uint32_t* r, uint32_t a) {
    asm volatile("ldmatrix.sync.aligned.m8n8.x4.shared.b16 {%0,%1,%2,%3}, [%4];"
        : "=r"(r[0]), "=r"(r[1]), "=r"(r[2]), "=r"(r[3]) : "r"(a));
}
__device__ __forceinline__ void cpa16(uint32_t s, const void* g) {
    asm volatile("cp.async.cg.shared.global [%0], [%1], 16;" :: "r"(s), "l"(g));
}
#define CPA_COMMIT() asm volatile("cp.async.commit_group;" ::: "memory")
#define CPA_WAIT2()  asm volatile("cp.async.wait_group 2;" ::: "memory")

// ---------------------------------------------------------------------------
// fp16 mma.sync GEMM:  D[M,N] = alpha * A[M,K] * B[N,K]^T  (+ epilogue)
//   A,B: __half K-major rows (stride K). Block 128 x NB (NB=128: 256 thr,
//   8 warps 4m x 2n; NB=64: 128 thr, 4 warps). Warp tile 32x64.
//   BK=16 (one m16n8k16 k-step), 4-stage cp.async.
//   Smem row stride 24 halves (48 B = 12 words): ldmatrix phase banks
//   12r mod 32 = {0,12,24,4,16,28,8,20} -> conflict-free.
//   A frag: 1 ldsm4/mi (quadrants m0=r0-7 kLo, m1=r8-15 kLo, m2=r0-7 kHi,
//   m3=r8-15 kHi -> a0..a3).  B frag: 1 ldsm4 per ni-pair.
//   EPI 0: half out = alpha*acc (+ bM[m] if BMODE==1, + bN[n] if BMODE==2)
//   EPI 1: float out = bng[m]*BN_INV*(acc+bM[m]) + bnb[m] + resid[m*ldc+n]
//   EPI 2: EPI1 value v; additionally out2 = v * cw[bz*M + m]
// ---------------------------------------------------------------------------
constexpr int SAB  = 48;               // smem row stride in bytes (32 + 16)
constexpr int NSTG = 4;

template<int EPI, int BMODE, int NB>
__global__ void __launch_bounds__(NB * 2, (NB == 128) ? 2 : 3)
tgemm(const __half* __restrict__ A, const __half* __restrict__ B,
      void* __restrict__ Co,
      int K, int ldc, long strA, long strB, long strC, float alpha,
      const float* __restrict__ bM, const float* __restrict__ bN,
      const float* __restrict__ bng, const float* __restrict__ bnb,
      const float* __restrict__ resid, long sR,
      const float* __restrict__ cw, float* __restrict__ out2)
{
    constexpr int AWB    = 128 * SAB;          // bytes of A per stage
    constexpr int STAGEB = (128 + NB) * SAB;

    extern __shared__ uint32_t sm[];
    const uint32_t smb = smem_u32(sm);

    const int tid = threadIdx.x, lane = tid & 31, wid = tid >> 5;
    const int wm = wid & 3, wn = wid >> 2;     // wn in [0, NB/64)
    const int bz = blockIdx.z;
    const int bm = blockIdx.y * 128, bn = blockIdx.x * NB;

    // ---- loader addressing (rows of 16 halves = 32 B = 2 cpa16) ----
    const __half* agp;  uint32_t asp;
    const __half* bgp;  uint32_t bsp;
    if constexpr (NB == 128) {
        const int lrow = tid & 127;
        const bool isA = tid < 128;
        agp = (isA ? A + (long)bz * strA + (long)(bm + lrow) * K
                   : B + (long)bz * strB + (long)(bn + lrow) * K);
        asp = smb + (uint32_t)((isA ? 0 : AWB) + lrow * SAB);
        bgp = nullptr; bsp = 0;
    } else {
        agp = A + (long)bz * strA + (long)(bm + tid) * K;
        asp = smb + (uint32_t)(tid * SAB);
        bgp = B + (long)bz * strB + (long)(bn + (tid >> 1)) * K + (tid & 1) * 8;
        bsp = smb + (uint32_t)(AWB + (tid >> 1) * SAB + (tid & 1) * 16);
    }

    auto loadt = [&](int kt, int st) {
        const uint32_t so = (uint32_t)(st * STAGEB);
        const __half* gp = agp + kt * 16;
        cpa16(asp + so,      gp);
        if constexpr (NB == 128) {
            cpa16(asp + so + 16, gp + 8);
        } else {
            cpa16(asp + so + 16, gp + 8);
            cpa16(bsp + so, bgp + kt * 16);
        }
    };

    // ldmatrix lane addresses:
    // A: row = wm*32 + (lane&7) + 8*((lane>>3)&1), kHalf = lane>>4
    // B (pair p): row = wn*64 + p*16 + (lane&7) + 8*(lane>>4), kHalf = (lane>>3)&1
    const uint32_t aAddr = smb +
        (uint32_t)((wm * 32 + (lane & 7) + 8 * ((lane >> 3) & 1)) * SAB
                   + (lane >> 4) * 16);
    const uint32_t bAddr = smb +
        (uint32_t)(AWB + (wn * 64 + (lane & 7) + 8 * (lane >> 4)) * SAB
                   + ((lane >> 3) & 1) * 16);

    float acc[2][8][4];
    #pragma unroll
    for (int i = 0; i < 2; i++)
        #pragma unroll
        for (int j = 0; j < 8; j++)
            #pragma unroll
            for (int q = 0; q < 4; q++) acc[i][j][q] = 0.f;

    auto compute = [&](int st) {
        const uint32_t stoff = (uint32_t)(st * STAGEB);
        uint32_t af[2][4];
        ldsm4(af[0], aAddr + stoff);                 // mi=0 (rows +0..15)
        ldsm4(af[1], aAddr + stoff + 16 * SAB);      // mi=1 (rows +16..31)
        uint32_t bf[4][4];
        #pragma unroll
        for (int p = 0; p < 4; p++)
            ldsm4(bf[p], bAddr + stoff + (uint32_t)(p * 16 * SAB));
        #pragma unroll
        for (int ni = 0; ni < 8; ni++) {
            const uint32_t* bb = &bf[ni >> 1][(ni & 1) * 2];
            mma16(acc[0][ni], af[0], bb);
            mma16(acc[1][ni], af[1], bb);
        }
    };

    const int nk = K / 16;          // >= 16 for all GEMMs here
    loadt(0, 0); CPA_COMMIT();
    loadt(1, 1); CPA_COMMIT();
    loadt(2, 2); CPA_COMMIT();

    for (int kt = 0; kt < nk; kt++) {
        const int s = kt & 3;
        CPA_WAIT2();
        __syncthreads();
        if (kt + 3 < nk) loadt(kt + 3, (kt + 3) & 3);
        CPA_COMMIT();
        compute(s);
    }

    // ---- epilogue ----
    const int g = lane >> 2, t2 = (lane & 3) * 2;
    #pragma unroll
    for (int mi = 0; mi < 2; mi++) {
        #pragma unroll
        for (int half = 0; half < 2; half++) {
            const int m = bm + wm * 32 + mi * 16 + half * 8 + g;
            float addM = 0.f, sc = 1.f, be = 0.f, gwv = 0.f;
            if constexpr (EPI == 0) {
                if constexpr (BMODE == 1) addM = bM[m];
            } else {
                addM = bM[m]; sc = bng[m] * BN_INV; be = bnb[m];
            }
            const long obase = (long)bz * strC + (long)m * ldc;
            const float* rrow = nullptr;
            float* o2row = nullptr;
            if constexpr (EPI >= 1) rrow = resid + (long)bz * sR + (long)m * ldc;
            if constexpr (EPI == 2) {
                o2row = out2 + (long)bz * strC + (long)m * ldc;
                gwv = cw[(long)bz * (gridDim.y * 128) + m];
            }
            #pragma unroll
            for (int ni = 0; ni < 8; ni++) {
                const int n = bn + wn * 64 + ni * 8 + t2;
                const float c0 = acc[mi][ni][half * 2 + 0];
                const float c1 = acc[mi][ni][half * 2 + 1];
                if constexpr (EPI == 0) {
                    float ox = alpha * c0 + addM;
                    float oy = alpha * c1 + addM;
                    if constexpr (BMODE == 2) { ox += bN[n]; oy += bN[n + 1]; }
                    *(__half2*)((__half*)Co + obase + n) = __floats2half2_rn(ox, oy);
                } else {
                    float2 rv = *(const float2*)&rrow[n];
                    float2 o;
                    o.x = sc * (c0 + addM) + be + rv.x;
                    o.y = sc * (c1 + addM) + be + rv.y;
                    *(float2*)((float*)Co + obase + n) = o;
                    if constexpr (EPI == 2) {
                        float2 o2 = { o.x * gwv, o.y * gwv };
                        *(float2*)&o2row[n] = o2;
                    }
                }
            }
        }
    }
}

constexpr int GS128 = NSTG * (128 + 128) * SAB;   // 49152 B
constexpr int GS64  = NSTG * (128 + 64)  * SAB;   // 36864 B

// ---------------------------------------------------------------------------
// Merged weight rounding: 5 matrices float -> half in one launch
// ---------------------------------------------------------------------------
__global__ void round5_k(const float* s0, const float* s1, const float* s2,
                         const float* s3, const float* s4,
                         __half* d0, __half* d1, __half* d2, __half* d3, __half* d4,
                         int n4)
{
    const float* s; __half* d;
    switch (blockIdx.y) {
        case 0:  s = s0; d = d0; break;
        case 1:  s = s1; d = d1; break;
        case 2:  s = s2; d = d2; break;
        case 3:  s = s3; d = d3; break;
        default: s = s4; d = d4; break;
    }
    const int i = blockIdx.x * blockDim.x + threadIdx.x;
    if (i >= n4) return;
    float4 v = ((const float4*)s)[i];
    ((__half2*)d)[2 * i + 0] = __floats2half2_rn(v.x, v.y);
    ((__half2*)d)[2 * i + 1] = __floats2half2_rn(v.z, v.w);
}

// ---------------------------------------------------------------------------
// Transpose float -> half: src [rows][cols] fp32 -> dst [cols][rows] fp16
// ---------------------------------------------------------------------------
__global__ void transpose_f2h_k(const float* __restrict__ src, __half* __restrict__ dst,
                                int rows, int cols)
{
    __shared__ float t[32][33];
    const long bo = (long)blockIdx.z * rows * cols;
    const int c0 = blockIdx.x * 32, r0 = blockIdx.y * 32;
    const int tx = threadIdx.x, ty = threadIdx.y;
    #pragma unroll
    for (int i = 0; i < 32; i += 8)
        t[ty + i][tx] = src[bo + (long)(r0 + ty + i) * cols + c0 + tx];
    __syncthreads();
    #pragma unroll
    for (int i = 0; i < 32; i += 8)
        dst[bo + (long)(c0 + ty + i) * rows + r0 + tx] = __float2half_rn(t[tx][ty + i]);
}

// ---------------------------------------------------------------------------
// Transpose half -> half (for fT = transpose(f); bit-exact reuse)
// ---------------------------------------------------------------------------
__global__ void transpose_h_k(const __half* __restrict__ src, __half* __restrict__ dst,
                              int rows, int cols)
{
    __shared__ __half t[32][33];
    const long bo = (long)blockIdx.z * rows * cols;
    const int c0 = blockIdx.x * 32, r0 = blockIdx.y * 32;
    const int tx = threadIdx.x, ty = threadIdx.y;
    #pragma unroll
    for (int i = 0; i < 32; i += 8)
        t[ty + i][tx] = src[bo + (long)(r0 + ty + i) * cols + c0 + tx];
    __syncthreads();
    #pragma unroll
    for (int i = 0; i < 32; i += 8)
        dst[bo + (long)(c0 + ty + i) * rows + r0 + tx] = t[tx][ty + i];
}

// ---------------------------------------------------------------------------
// Avg+Max pooling: one warp per (b,c)   (non_aim is fp32)
// ---------------------------------------------------------------------------
__global__ void pool_k(const float* __restrict__ na, float* __restrict__ pooled)
{
    const int gw = (int)((blockIdx.x * (long)blockDim.x + threadIdx.x) >> 5);
    const int lane = threadIdx.x & 31;
    if (gw >= Bc * C) return;
    const float* p = na + (long)gw * Na;
    float s = 0.f, m = -3.4e38f;
    for (int i = lane; i < Na; i += 32) { float v = p[i]; s += v; m = fmaxf(m, v); }
    #pragma unroll
    for (int o = 16; o; o >>= 1) {
        s += __shfl_xor_sync(0xffffffffu, s, o);
        m = fmaxf(m, __shfl_xor_sync(0xffffffffu, m, o));
    }
    if (lane == 0) {
        const int b = gw / C, c = gw % C;
        pooled[(long)b * 2 * C + c]     = s * (1.f / Na);
        pooled[(long)b * 2 * C + C + c] = m;
    }
}

// ---------------------------------------------------------------------------
// Channel gate MLP + sigmoid, one block per batch
// ---------------------------------------------------------------------------
__global__ void gate_k(const float* __restrict__ pooled,
                       const float* __restrict__ w1, const float* __restrict__ b1,
                       const float* __restrict__ w2, const float* __restrict__ b2,
                       float* __restrict__ cw)
{
    __shared__ float sv[2 * C];
    __shared__ float h[2][R];
    __shared__ float hs[R];
    const int b = blockIdx.x, tid = threadIdx.x;
    for (int i = tid; i < 2 * C; i += blockDim.x)
        sv[i] = pooled[(long)b * 2 * C + i];
    __syncthreads();
    if (tid < 2 * R) {
        const int which = tid / R, r = tid % R;
        const float* v = sv + which * C;
        const float* wr = w1 + r * C;
        float acc = b1[r];
        for (int c = 0; c < C; c++) acc += wr[c] * v[c];
        h[which][r] = fmaxf(acc, 0.f);
    }
    __syncthreads();
    if (tid < R) hs[tid] = h[0][tid] + h[1][tid];
    __syncthreads();
    for (int c = tid; c < C; c += blockDim.x) {
        const float* wc = w2 + c * R;
        float acc = 2.f * b2[c];
        #pragma unroll 8
        for (int r = 0; r < R; r++) acc += wc[r] * hs[r];
        cw[(long)b * C + c] = 1.f / (1.f + expf(-acc));
    }
}

// ---------------------------------------------------------------------------
// Channel scaling (act_aim): dst = src * cw[b*C + c]
// ---------------------------------------------------------------------------
__global__ void scale_k(const float* __restrict__ src, const float* __restrict__ cw,
                        float* __restrict__ dst, int q_div, long total4)
{
    const long i = blockIdx.x * (long)blockDim.x + threadIdx.x;
    if (i >= total4) return;
    const float w = cw[i / q_div];
    float4 v = ((const float4*)src)[i];
    v.x *= w; v.y *= w; v.z *= w; v.w *= w;
    ((float4*)dst)[i] = v;
}

// ---------------------------------------------------------------------------
// Launch
// ---------------------------------------------------------------------------
extern "C" void kernel_launch(void* const* d_in, const int* in_sizes, int n_in,
                              void* d_out, int out_size)
{
    (void)in_sizes; (void)n_in; (void)out_size;
    const float* detect = (const float*)d_in[0];
    const float* aim    = (const float*)d_in[1];
    const float* g_w    = (const float*)d_in[2];
    const float* g_b    = (const float*)d_in[3];
    const float* th_w   = (const float*)d_in[4];
    const float* th_b   = (const float*)d_in[5];
    const float* ph_w   = (const float*)d_in[6];
    const float* ph_b   = (const float*)d_in[7];
    const float* W_w    = (const float*)d_in[8];
    const float* W_b    = (const float*)d_in[9];
    const float* W_bn_g = (const float*)d_in[10];
    const float* W_bn_b = (const float*)d_in[11];
    const float* Q_w    = (const float*)d_in[12];
    const float* Q_b    = (const float*)d_in[13];
    const float* Q_bn_g = (const float*)d_in[14];
    const float* Q_bn_b = (const float*)d_in[15];
    const float* m1_w   = (const float*)d_in[16];
    const float* m1_b   = (const float*)d_in[17];
    const float* m2_w   = (const float*)d_in[18];
    const float* m2_b   = (const float*)d_in[19];
    float* out = (float*)d_out;

    __half *detT, *aimT, *dx, *phx, *ax, *thx, *fm, *fT, *nap, *ndp;
    __half *gwr, *thwr, *phwr, *Wwr, *Qwr;
    float *nonaim, *pooled;
    cudaGetSymbolAddress((void**)&detT,   g_detT);
    cudaGetSymbolAddress((void**)&aimT,   g_aimT);
    cudaGetSymbolAddress((void**)&dx,     g_dx);
    cudaGetSymbolAddress((void**)&phx,    g_phx);
    cudaGetSymbolAddress((void**)&ax,     g_ax);
    cudaGetSymbolAddress((void**)&thx,    g_thx);
    cudaGetSymbolAddress((void**)&fm,     g_fm);
    cudaGetSymbolAddress((void**)&fT,     g_fT);
    cudaGetSymbolAddress((void**)&nap,    g_nap);
    cudaGetSymbolAddress((void**)&ndp,    g_ndp);
    cudaGetSymbolAddress((void**)&nonaim, g_nonaim);
    cudaGetSymbolAddress((void**)&pooled, g_pooled);
    cudaGetSymbolAddress((void**)&gwr,    g_gwr);
    cudaGetSymbolAddress((void**)&thwr,   g_thwr);
    cudaGetSymbolAddress((void**)&phwr,   g_phwr);
    cudaGetSymbolAddress((void**)&Wwr,    g_Wwr);
    cudaGetSymbolAddress((void**)&Qwr,    g_Qwr);

    const long offNonDet = 0;
    const long offActDet = (long)Bc * C * Nd;
    const long offActAim = 2 * offActDet;
    const long offCw     = offActAim + (long)Bc * C * Na;

    cudaFuncSetAttribute(tgemm<0,1,128>, cudaFuncAttributeMaxDynamicSharedMemorySize, GS128);
    cudaFuncSetAttribute(tgemm<0,2,128>, cudaFuncAttributeMaxDynamicSharedMemorySize, GS128);
    cudaFuncSetAttribute(tgemm<0,0,128>, cudaFuncAttributeMaxDynamicSharedMemorySize, GS128);
    cudaFuncSetAttribute(tgemm<2,0,128>, cudaFuncAttributeMaxDynamicSharedMemorySize, GS128);
    cudaFuncSetAttribute(tgemm<0,1,64>,  cudaFuncAttributeMaxDynamicSharedMemorySize, GS64);
    cudaFuncSetAttribute(tgemm<0,2,64>,  cudaFuncAttributeMaxDynamicSharedMemorySize, GS64);
    cudaFuncSetAttribute(tgemm<0,0,64>,  cudaFuncAttributeMaxDynamicSharedMemorySize, GS64);
    cudaFuncSetAttribute(tgemm<1,0,64>,  cudaFuncAttributeMaxDynamicSharedMemorySize, GS64);

    const int n4 = (Ci * C) / 4;

    // prologue: transposes (fp32 -> fp16) + merged weight conversion
    transpose_f2h_k<<<dim3(Nd / 32, C / 32, Bc), dim3(32, 8)>>>(detect, detT, C, Nd);
    transpose_f2h_k<<<dim3(Na / 32, C / 32, Bc), dim3(32, 8)>>>(aim,    aimT, C, Na);
    round5_k<<<dim3((n4 + 255) / 256, 5), 256>>>(
        g_w, th_w, ph_w, W_w, Q_w, gwr, thwr, phwr, Wwr, Qwr, n4);

    // G1: d_x[Ci,Nd] = gwr * detT^T + g_b[m]          (NB=128, 576 CTAs)
    tgemm<0,1,128><<<dim3(Nd/128, Ci/128, Bc), 256, GS128>>>(
        gwr, detT, dx, C, Nd, 0, (long)Nd*C, (long)Ci*Nd, 1.f,
        g_b, nullptr, nullptr, nullptr, nullptr, 0, nullptr, nullptr);
    // G2: phi_x[Nd,Ci] = detT * phwr^T + ph_b[n]      (NB=128, 576)
    tgemm<0,2,128><<<dim3(Ci/128, Nd/128, Bc), 256, GS128>>>(
        detT, phwr, phx, C, Ci, (long)Nd*C, 0, (long)Nd*Ci, 1.f,
        nullptr, ph_b, nullptr, nullptr, nullptr, 0, nullptr, nullptr);
    // G3: a_x[Ci,Na] = gwr * aimT^T + g_b[m]          (NB=64, 128 CTAs)
    tgemm<0,1,64><<<dim3(Na/64, Ci/128, Bc), 128, GS64>>>(
        gwr, aimT, ax, C, Na, 0, (long)Na*C, (long)Ci*Na, 1.f,
        g_b, nullptr, nullptr, nullptr, nullptr, 0, nullptr, nullptr);
    // G4: theta_x[Na,Ci] = aimT * thwr^T + th_b[n]    (NB=64, 128)
    tgemm<0,2,64><<<dim3(Ci/64, Na/128, Bc), 128, GS64>>>(
        aimT, thwr, thx, C, Ci, (long)Na*C, 0, (long)Na*Ci, 1.f,
        nullptr, th_b, nullptr, nullptr, nullptr, 0, nullptr, nullptr);
    // G5: f[Na,Nd] = theta * phi^T                    (NB=128, 288)
    tgemm<0,0,128><<<dim3(Nd/128, Na/128, Bc), 256, GS128>>>(
        thx, phx, fm, Ci, Nd, (long)Na*Ci, (long)Nd*Ci, (long)Na*Nd, 1.f,
        nullptr, nullptr, nullptr, nullptr, nullptr, 0, nullptr, nullptr);
    // T5b: fT[Nd,Na] = transpose(f)  (bit-identical to a fT GEMM)
    transpose_h_k<<<dim3(Nd / 32, Na / 32, Bc), dim3(32, 8)>>>(fm, fT, Na, Nd);
    // G6: nap[Na,Ci] = (1/Nd) f * d_x^T               (NB=64, 128)
    tgemm<0,0,64><<<dim3(Ci/64, Na/128, Bc), 128, GS64>>>(
        fm, dx, nap, Nd, Ci, (long)Na*Nd, (long)Ci*Nd, (long)Na*Ci, 1.f/Nd,
        nullptr, nullptr, nullptr, nullptr, nullptr, 0, nullptr, nullptr);
    // G7: ndp[Nd,Ci] = (1/Na) fT * a_x^T              (NB=128, 576)
    tgemm<0,0,128><<<dim3(Ci/128, Nd/128, Bc), 256, GS128>>>(
        fT, ax, ndp, Na, Ci, (long)Nd*Na, (long)Ci*Na, (long)Nd*Ci, 1.f/Na,
        nullptr, nullptr, nullptr, nullptr, nullptr, 0, nullptr, nullptr);
    // G8: non_aim[C,Na] = bn(Wwr * nap^T + W_b) + aim (NB=64, 256; fp32 out)
    tgemm<1,0,64><<<dim3(Na/64, C/128, Bc), 128, GS64>>>(
        Wwr, nap, nonaim, Ci, Na, 0, (long)Na*Ci, (long)C*Na, 1.f,
        W_b, nullptr, W_bn_g, W_bn_b, aim, (long)C*Na, nullptr, nullptr);
    // pool + gate
    pool_k<<<(Bc * C) / 8, 256>>>(nonaim, pooled);
    gate_k<<<Bc, 256>>>(pooled, m1_w, m1_b, m2_w, m2_b, out + offCw);
    // G9: non_det[C,Nd] = bn(Qwr * ndp^T + Q_b) + detect ; act_det fused
    tgemm<2,0,128><<<dim3(Nd/128, C/128, Bc), 256, GS128>>>(
        Qwr, ndp, out + offNonDet, Ci, Nd, 0, (long)Nd*Ci, (long)C*Nd, 1.f,
        Q_b, nullptr, Q_bn_g, Q_bn_b, detect, (long)C*Nd,
        out + offCw, out + offActDet);
    // act_aim = non_aim * cw
    const long t4a = (long)Bc * C * Na / 4;
    scale_k<<<(unsigned)((t4a + 255) / 256), 256>>>(
        nonaim, out + offCw, out + offActAim, Na / 4, t4a);
}